// round 14
// baseline (speedup 1.0000x reference)
#include <cuda_runtime.h>
#include <cuda_bf16.h>
#include <math.h>

// ---------------- problem constants ----------------
#define BATCH 4
#define HW    112
#define NTOK  12544
#define CDIM  256
#define GH    4
#define HD    32
#define GD    128
#define LD    128
#define HID   1024
#define WSZ   7
#define MPOOL 256
#define ROWS  (BATCH*NTOK)
#define HALFR (ROWS/2)
#define ATT_SCALE 0.17677669529663687f

#define PADK  40
#define TILEB (128*PADK)

// ---------------- scratch (device globals; no allocation) ----------------
__device__ __align__(256) __nv_bfloat16 g_xn_h [ROWS*CDIM];
__device__ __align__(256) __nv_bfloat16 g_xn_l [ROWS*CDIM];
__device__ __align__(256) __nv_bfloat16 g_xrn_h[ROWS*CDIM];
__device__ __align__(256) __nv_bfloat16 g_xrn_l[ROWS*CDIM];
__device__ __align__(256) __nv_bfloat16 g_pool_h[BATCH*MPOOL*CDIM];
__device__ __align__(256) __nv_bfloat16 g_pool_l[BATCH*MPOOL*CDIM];
__device__ __align__(256) float g_qq [ROWS*256];         // [Gq | Lq]
__device__ __align__(256) float g_kv [BATCH*MPOOL*2*GD];
__device__ __align__(256) float g_kvl[ROWS*2*LD];
__device__ __align__(256) __nv_bfloat16 g_att_h[ROWS*256];  // [gattn | lattn]
__device__ __align__(256) __nv_bfloat16 g_att_l[ROWS*256];
__device__ __align__(256) float g_cat[ROWS*CDIM];
__device__ __align__(256) __nv_bfloat16 g_ln2_h[ROWS*CDIM];
__device__ __align__(256) __nv_bfloat16 g_ln2_l[ROWS*CDIM];
__device__ __align__(256) float g_h1 [ROWS*HID];
__device__ __align__(256) __nv_bfloat16 g_h2_h[ROWS*HID];
__device__ __align__(256) __nv_bfloat16 g_h2_l[ROWS*HID];
// transposed split weights [N][K] + merged bias
__device__ __align__(256) __nv_bfloat16 w_q_h [256*CDIM];
__device__ __align__(256) __nv_bfloat16 w_q_l [256*CDIM];
__device__ __align__(256) __nv_bfloat16 w_kv_h[256*CDIM];
__device__ __align__(256) __nv_bfloat16 w_kv_l[256*CDIM];
__device__ __align__(256) __nv_bfloat16 w_lkv_h[256*CDIM];
__device__ __align__(256) __nv_bfloat16 w_lkv_l[256*CDIM];
__device__ __align__(256) __nv_bfloat16 w_gp_h [GD*GD];
__device__ __align__(256) __nv_bfloat16 w_gp_l [GD*GD];
__device__ __align__(256) __nv_bfloat16 w_lp_h [LD*LD];
__device__ __align__(256) __nv_bfloat16 w_lp_l [LD*LD];
__device__ __align__(256) __nv_bfloat16 w_fc1_h[HID*CDIM];
__device__ __align__(256) __nv_bfloat16 w_fc1_l[HID*CDIM];
__device__ __align__(256) __nv_bfloat16 w_fc2_h[CDIM*HID];
__device__ __align__(256) __nv_bfloat16 w_fc2_l[CDIM*HID];
__device__ __align__(256) float b_q[256];

// ---------------- helpers ----------------
__device__ __forceinline__ void split_store4(__nv_bfloat16* ph, __nv_bfloat16* pl, float4 v)
{
    __nv_bfloat16 hx = __float2bfloat16(v.x);
    __nv_bfloat16 hy = __float2bfloat16(v.y);
    __nv_bfloat16 hz = __float2bfloat16(v.z);
    __nv_bfloat16 hw = __float2bfloat16(v.w);
    __nv_bfloat162 h0 = __nv_bfloat162(hx, hy);
    __nv_bfloat162 h1 = __nv_bfloat162(hz, hw);
    __nv_bfloat162 l0 = __nv_bfloat162(__float2bfloat16(v.x - __bfloat162float(hx)),
                                       __float2bfloat16(v.y - __bfloat162float(hy)));
    __nv_bfloat162 l1 = __nv_bfloat162(__float2bfloat16(v.z - __bfloat162float(hz)),
                                       __float2bfloat16(v.w - __bfloat162float(hw)));
    ((__nv_bfloat162*)ph)[0] = h0;
    ((__nv_bfloat162*)ph)[1] = h1;
    ((__nv_bfloat162*)pl)[0] = l0;
    ((__nv_bfloat162*)pl)[1] = l1;
}

__device__ __forceinline__ unsigned smem_u32(const void* p)
{
    return (unsigned)__cvta_generic_to_shared(p);
}

__device__ __forceinline__ void ldsm4(unsigned* r, unsigned addr)
{
    asm volatile("ldmatrix.sync.aligned.m8n8.x4.shared.b16 {%0,%1,%2,%3}, [%4];"
        : "=r"(r[0]), "=r"(r[1]), "=r"(r[2]), "=r"(r[3]) : "r"(addr));
}

__device__ __forceinline__ void mma_bf16(float* c, const unsigned* a, const unsigned* b)
{
    asm volatile("mma.sync.aligned.m16n8k16.row.col.f32.bf16.bf16.f32 "
        "{%0,%1,%2,%3},{%4,%5,%6,%7},{%8,%9},{%0,%1,%2,%3};"
        : "+f"(c[0]), "+f"(c[1]), "+f"(c[2]), "+f"(c[3])
        : "r"(a[0]), "r"(a[1]), "r"(a[2]), "r"(a[3]), "r"(b[0]), "r"(b[1]));
}

__device__ __forceinline__ void cpa16(unsigned saddr, const void* g)
{
    asm volatile("cp.async.cg.shared.global [%0], [%1], 16;" :: "r"(saddr), "l"(g) : "memory");
}

// ---- packed f32x2 math ----
__device__ __forceinline__ void fma2(unsigned long long& d, unsigned long long a,
                                     unsigned long long b)
{
    asm("fma.rn.f32x2 %0, %1, %2, %0;" : "+l"(d) : "l"(a), "l"(b));
}

__device__ __forceinline__ void mul2(unsigned long long& d, unsigned long long c)
{
    asm("mul.rn.f32x2 %0, %0, %1;" : "+l"(d) : "l"(c));
}

__device__ __forceinline__ unsigned long long pack2(float x)
{
    unsigned long long r;
    asm("mov.b64 %0, {%1, %1};" : "=l"(r) : "f"(x));
    return r;
}

__device__ __forceinline__ float2 unpack2(unsigned long long v)
{
    float2 f;
    asm("mov.b64 {%0, %1}, %2;" : "=f"(f.x), "=f"(f.y) : "l"(v));
    return f;
}

// stage loader: 256 threads, 4 tiles x 512 16B-chunks
__device__ __forceinline__ void gemm_stage(
    __nv_bfloat16* sbase, int tid,
    const __nv_bfloat16* Ah, const __nv_bfloat16* Al,
    const __nv_bfloat16* Bh, const __nv_bfloat16* Bl,
    int bm, int bn, int K, int lda, int k0)
{
    __nv_bfloat16* sA0 = sbase;
    __nv_bfloat16* sA1 = sbase + TILEB;
    __nv_bfloat16* sB0 = sbase + 2*TILEB;
    __nv_bfloat16* sB1 = sbase + 3*TILEB;
    #pragma unroll
    for (int j = 0; j < 2; j++) {
        int u = tid + 256*j;
        int row = u >> 2;
        int qq = u & 3;
        int so = row * PADK + qq * 8;
        size_t gA = (size_t)(bm + row) * lda + k0 + qq * 8;
        size_t gB = (size_t)(bn + row) * K + k0 + qq * 8;
        cpa16(smem_u32(sA0 + so), Ah + gA);
        cpa16(smem_u32(sA1 + so), Al + gA);
        cpa16(smem_u32(sB0 + so), Bh + gB);
        cpa16(smem_u32(sB1 + so), Bl + gB);
    }
}

// ---------------- single-launch weight transpose + split ----------------
__device__ __forceinline__ void wt_store(__nv_bfloat16* hi, __nv_bfloat16* lo,
                                         int t, float v)
{
    __nv_bfloat16 h = __float2bfloat16(v);
    hi[t] = h;
    lo[t] = __float2bfloat16(v - __bfloat162float(h));
}

__global__ void wtrans_all(const float* __restrict__ Gq, const float* __restrict__ Gkv,
                           const float* __restrict__ Gp, const float* __restrict__ Lq,
                           const float* __restrict__ Lkv, const float* __restrict__ Lp,
                           const float* __restrict__ fc1, const float* __restrict__ fc2,
                           const float* __restrict__ Gq_b, const float* __restrict__ Lq_b)
{
    int t = blockIdx.x * blockDim.x + threadIdx.x;
    if (t < 65536) {
        int n = t >> 8;
        int k = t & 255;
        float v = (n < 128) ? Gq[(size_t)k*128 + n] : Lq[(size_t)k*128 + (n-128)];
        wt_store(w_q_h, w_q_l, t, v);
    } else if (t < 131072) {
        int u = t - 65536;
        int n = u >> 8;
        int k = u & 255;
        wt_store(w_kv_h, w_kv_l, u, Gkv[(size_t)k*256 + n]);
    } else if (t < 196608) {
        int u = t - 131072;
        int n = u >> 8;
        int k = u & 255;
        wt_store(w_lkv_h, w_lkv_l, u, Lkv[(size_t)k*256 + n]);
    } else if (t < 212992) {
        int u = t - 196608;
        int n = u >> 7;
        int k = u & 127;
        wt_store(w_gp_h, w_gp_l, u, Gp[(size_t)k*128 + n]);
    } else if (t < 229376) {
        int u = t - 212992;
        int n = u >> 7;
        int k = u & 127;
        wt_store(w_lp_h, w_lp_l, u, Lp[(size_t)k*128 + n]);
    } else if (t < 491520) {
        int u = t - 229376;
        int n = u >> 8;
        int k = u & 255;
        wt_store(w_fc1_h, w_fc1_l, u, fc1[(size_t)k*1024 + n]);
    } else if (t < 753664) {
        int u = t - 491520;
        int n = u / 1024;
        int k = u - n * 1024;
        wt_store(w_fc2_h, w_fc2_l, u, fc2[(size_t)k*256 + n]);
    } else if (t < 753920) {
        int u = t - 753664;
        b_q[u] = (u < 128) ? Gq_b[u] : Lq_b[u-128];
    }
}

// ---------------- LayerNorm (ln1) ----------------
__global__ void ln_kernel(const float* __restrict__ x, const float* __restrict__ g,
                          const float* __restrict__ b,
                          __nv_bfloat16* __restrict__ oh, __nv_bfloat16* __restrict__ ol,
                          int rows)
{
    int gw   = (blockIdx.x * blockDim.x + threadIdx.x) >> 5;
    int lane = threadIdx.x & 31;
    if (gw >= rows) return;
    const float4* xr = (const float4*)(x + (size_t)gw * CDIM);
    float4 v0 = xr[lane];
    float4 v1 = xr[lane + 32];
    float s  = v0.x+v0.y+v0.z+v0.w + v1.x+v1.y+v1.z+v1.w;
    float ss = v0.x*v0.x+v0.y*v0.y+v0.z*v0.z+v0.w*v0.w
             + v1.x*v1.x+v1.y*v1.y+v1.z*v1.z+v1.w*v1.w;
    #pragma unroll
    for (int o = 16; o; o >>= 1) {
        s  += __shfl_xor_sync(0xffffffffu, s,  o);
        ss += __shfl_xor_sync(0xffffffffu, ss, o);
    }
    float mean = s * (1.0f/CDIM);
    float var  = ss * (1.0f/CDIM) - mean*mean;
    float inv  = rsqrtf(var + 1e-5f);
    const float4* g4 = (const float4*)g;
    const float4* b4 = (const float4*)b;
    float4 G0 = g4[lane];
    float4 B0 = b4[lane];
    float4 G1 = g4[lane+32];
    float4 B1 = b4[lane+32];
    float4 o0, o1;
    o0.x = (v0.x-mean)*inv*G0.x + B0.x;
    o0.y = (v0.y-mean)*inv*G0.y + B0.y;
    o0.z = (v0.z-mean)*inv*G0.z + B0.z;
    o0.w = (v0.w-mean)*inv*G0.w + B0.w;
    o1.x = (v1.x-mean)*inv*G1.x + B1.x;
    o1.y = (v1.y-mean)*inv*G1.y + B1.y;
    o1.z = (v1.z-mean)*inv*G1.z + B1.z;
    o1.w = (v1.w-mean)*inv*G1.w + B1.w;
    size_t base = (size_t)gw * CDIM + lane * 4;
    split_store4(oh + base,       ol + base,       o0);
    split_store4(oh + base + 128, ol + base + 128, o1);
}

// ---------------- fused residual add + LayerNorm (ln2) ----------------
__global__ void addln_kernel(const float* __restrict__ x, const float* __restrict__ cat,
                             const float* __restrict__ g, const float* __restrict__ b,
                             float* __restrict__ out,
                             __nv_bfloat16* __restrict__ oh, __nv_bfloat16* __restrict__ ol)
{
    int gw   = (blockIdx.x * blockDim.x + threadIdx.x) >> 5;
    int lane = threadIdx.x & 31;
    const float4* xr = (const float4*)(x + (size_t)gw * CDIM);
    const float4* cr = (const float4*)(cat + (size_t)gw * CDIM);
    float4 a0 = xr[lane];
    float4 a1 = xr[lane + 32];
    float4 c0 = cr[lane];
    float4 c1 = cr[lane + 32];
    float4 v0 = make_float4(a0.x+c0.x, a0.y+c0.y, a0.z+c0.z, a0.w+c0.w);
    float4 v1 = make_float4(a1.x+c1.x, a1.y+c1.y, a1.z+c1.z, a1.w+c1.w);
    float4* orow = (float4*)(out + (size_t)gw * CDIM);
    orow[lane]      = v0;
    orow[lane + 32] = v1;
    float s  = v0.x+v0.y+v0.z+v0.w + v1.x+v1.y+v1.z+v1.w;
    float ss = v0.x*v0.x+v0.y*v0.y+v0.z*v0.z+v0.w*v0.w
             + v1.x*v1.x+v1.y*v1.y+v1.z*v1.z+v1.w*v1.w;
    #pragma unroll
    for (int o = 16; o; o >>= 1) {
        s  += __shfl_xor_sync(0xffffffffu, s,  o);
        ss += __shfl_xor_sync(0xffffffffu, ss, o);
    }
    float mean = s * (1.0f/CDIM);
    float var  = ss * (1.0f/CDIM) - mean*mean;
    float inv  = rsqrtf(var + 1e-5f);
    const float4* g4 = (const float4*)g;
    const float4* b4 = (const float4*)b;
    float4 G0 = g4[lane];
    float4 B0 = b4[lane];
    float4 G1 = g4[lane+32];
    float4 B1 = b4[lane+32];
    float4 o0, o1;
    o0.x = (v0.x-mean)*inv*G0.x + B0.x;
    o0.y = (v0.y-mean)*inv*G0.y + B0.y;
    o0.z = (v0.z-mean)*inv*G0.z + B0.z;
    o0.w = (v0.w-mean)*inv*G0.w + B0.w;
    o1.x = (v1.x-mean)*inv*G1.x + B1.x;
    o1.y = (v1.y-mean)*inv*G1.y + B1.y;
    o1.z = (v1.z-mean)*inv*G1.z + B1.z;
    o1.w = (v1.w-mean)*inv*G1.w + B1.w;
    size_t base = (size_t)gw * CDIM + lane * 4;
    split_store4(oh + base,       ol + base,       o0);
    split_store4(oh + base + 128, ol + base + 128, o1);
}

// ---------------- 7x7 mean pooling ----------------
__global__ void pool_kernel(const __nv_bfloat16* __restrict__ xh,
                            const __nv_bfloat16* __restrict__ xl,
                            __nv_bfloat16* __restrict__ ph, __nv_bfloat16* __restrict__ pl)
{
    int t = blockIdx.x * blockDim.x + threadIdx.x;
    int c = t & 255;
    int g = (t >> 8) & 255;
    int b = t >> 16;
    int gy = g >> 4;
    int gx = g & 15;
    float s = 0.0f;
    #pragma unroll
    for (int py = 0; py < WSZ; py++) {
        int rowbase = (gy*WSZ + py) * HW + gx*WSZ;
        #pragma unroll
        for (int px = 0; px < WSZ; px++) {
            size_t idx = ((size_t)b*NTOK + rowbase + px) * CDIM + c;
            s += __bfloat162float(xh[idx]) + __bfloat162float(xl[idx]);
        }
    }
    float v = s * (1.0f/49.0f);
    __nv_bfloat16 h = __float2bfloat16(v);
    ph[t] = h;
    pl[t] = __float2bfloat16(v - __bfloat162float(h));
}

// ---------------- tensor-core bf16x3 GEMM (R7-best) ----------------
__global__ void __launch_bounds__(256, 2) mma_gemm(
    const __nv_bfloat16* __restrict__ Ah, const __nv_bfloat16* __restrict__ Al,
    const __nv_bfloat16* __restrict__ Bh, const __nv_bfloat16* __restrict__ Bl,
    const float* __restrict__ bias, const float* __restrict__ addsrc,
    float* __restrict__ C, int M, int N, int K, int lda, int ldc, int coff)
{
    extern __shared__ __nv_bfloat16 sh[];
    int tid  = threadIdx.x;
    int lane = tid & 31;
    int warp = tid >> 5;
    int wm = (warp & 3) * 32;
    int wn = (warp >> 2) * 64;
    int bm = blockIdx.y * 128;
    int bn = blockIdx.x * 128;

    float acc[2][8][4];
    #pragma unroll
    for (int i = 0; i < 2; i++) {
        #pragma unroll
        for (int j = 0; j < 8; j++) {
            #pragma unroll
            for (int e = 0; e < 4; e++) {
                acc[i][j][e] = 0.0f;
            }
        }
    }

    int nIter = K >> 5;

    gemm_stage(sh, tid, Ah, Al, Bh, Bl, bm, bn, K, lda, 0);
    asm volatile("cp.async.commit_group;" ::: "memory");

    for (int it = 0; it < nIter; it++) {
        int st = it & 1;
        if (it + 1 < nIter) {
            gemm_stage(sh + (st^1)*4*TILEB, tid, Ah, Al, Bh, Bl, bm, bn, K, lda, (it+1) << 5);
            asm volatile("cp.async.commit_group;" ::: "memory");
            asm volatile("cp.async.wait_group 1;" ::: "memory");
        } else {
            asm volatile("cp.async.wait_group 0;" ::: "memory");
        }
        __syncthreads();

        const __nv_bfloat16* cA0 = sh + st*4*TILEB;
        const __nv_bfloat16* cA1 = cA0 + TILEB;
        const __nv_bfloat16* cB0 = cA0 + 2*TILEB;
        const __nv_bfloat16* cB1 = cA0 + 3*TILEB;

        #pragma unroll
        for (int kk = 0; kk < 2; kk++) {
            unsigned afh[2][4];
            unsigned afl[2][4];
            #pragma unroll
            for (int mi = 0; mi < 2; mi++) {
                int row = wm + mi*16 + (lane & 15);
                int col = kk*16 + (lane >> 4) * 8;
                ldsm4(afh[mi], smem_u32(cA0 + row*PADK + col));
                ldsm4(afl[mi], smem_u32(cA1 + row*PADK + col));
            }
            #pragma unroll
            for (int np = 0; np < 4; np++) {
                unsigned bfh[4];
                unsigned bfl[4];
                int row = wn + np*16 + (lane >> 4) * 8 + (lane & 7);
                int col = kk*16 + ((lane >> 3) & 1) * 8;
                ldsm4(bfh, smem_u32(cB0 + row*PADK + col));
                ldsm4(bfl, smem_u32(cB1 + row*PADK + col));
                #pragma unroll
                for (int mi = 0; mi < 2; mi++) {
                    mma_bf16(acc[mi][2*np],   afh[mi], &bfh[0]);
                    mma_bf16(acc[mi][2*np+1], afh[mi], &bfh[2]);
                    mma_bf16(acc[mi][2*np],   afh[mi], &bfl[0]);
                    mma_bf16(acc[mi][2*np+1], afh[mi], &bfl[2]);
                    mma_bf16(acc[mi][2*np],   afl[mi], &bfh[0]);
                    mma_bf16(acc[mi][2*np+1], afl[mi], &bfh[2]);
                }
            }
        }
        __syncthreads();
    }

    int gg = lane >> 2;
    int t2 = (lane & 3) * 2;
    #pragma unroll
    for (int mi = 0; mi < 2; mi++) {
        #pragma unroll
        for (int half = 0; half < 2; half++) {
            int row = bm + wm + mi*16 + gg + half*8;
            #pragma unroll
            for (int ni = 0; ni < 8; ni++) {
                int col = bn + wn + ni*8 + t2;
                float2 bv = *(const float2*)&bias[col];
                float v0 = acc[mi][ni][half*2 + 0] + bv.x;
                float v1 = acc[mi][ni][half*2 + 1] + bv.y;
                size_t off = (size_t)row * ldc + coff + col;
                if (addsrc) {
                    float2 sv = *(const float2*)&addsrc[off];
                    v0 += sv.x;
                    v1 += sv.y;
                }
                *(float2*)&C[off] = make_float2(v0, v1);
            }
        }
    }
}

// ---------------- global attention (R7: f32x2, 2-chunk KV) ----------------
__global__ void __launch_bounds__(128) gattn_kernel(
    const float* __restrict__ q, const float* __restrict__ kv,
    __nv_bfloat16* __restrict__ oh, __nv_bfloat16* __restrict__ ol)
{
    __shared__ float ks[128][HD];
    __shared__ float vs[128][HD];
    int bi = blockIdx.x;
    int qc = bi % (NTOK/128);
    int h  = (bi / (NTOK/128)) & (GH-1);
    int b  = bi / ((NTOK/128) * GH);
    int tid = threadIdx.x;
    int n   = qc*128 + tid;
    size_t qrow = (size_t)(b*NTOK + n) * 256 + h*HD;

    unsigned long long q2[16];
    {
        const ulonglong2* qp = (const ulonglong2*)&q[qrow];
        #pragma unroll
        for (int j = 0; j < 8; j++) {
            ulonglong2 t = qp[j];
            q2[2*j]   = t.x;
            q2[2*j+1] = t.y;
        }
    }

    float mx = -INFINITY;
    float l = 0.0f;
    unsigned long long a2[16];
    #pragma unroll
    for (int d = 0; d < 16; d++) {
        a2[d] = 0ULL;
    }

    for (int ch = 0; ch < 2; ch++) {
        #pragma unroll
        for (int j = 0; j < 8; j++) {
            int f4 = tid + 128*j;
            int m  = f4 >> 3;
            int d4 = (f4 & 7) * 4;
            size_t kvrow = (size_t)(b*MPOOL + ch*128 + m) * (2*GD) + h*HD;
            *(float4*)&ks[m][d4] = *(const float4*)&kv[kvrow + d4];
            *(float4*)&vs[m][d4] = *(const float4*)&kv[kvrow + GD + d4];
        }
        __syncthreads();
        for (int m = 0; m < 128; m++) {
            const ulonglong2* kp = (const ulonglong2*)ks[m];
            unsigned long long s0 = 0ULL, s1 = 0ULL, s2 = 0ULL, s3 = 0ULL;
            #pragma unroll
            for (int i = 0; i < 4; i++) {
                ulonglong2 ka = kp[2*i];
                ulonglong2 kb = kp[2*i+1];
                fma2(s0, q2[4*i+0], ka.x);
                fma2(s1, q2[4*i+1], ka.y);
                fma2(s2, q2[4*i+2], kb.x);
                fma2(s3, q2[4*i+3], kb.y);
            }
            float2 f0 = unpack2(s0);
            float2 f1 = unpack2(s1);
            float2 f2 = unpack2(s2);
            float2 f3 = unpack2(s3);
            float sdot = (f0.x + f0.y) + (f1.x + f1.y) + (f2.x + f2.y) + (f3.x + f3.y);
            float sc = sdot * ATT_SCALE;
            if (sc > mx) {
                float corr = __expf(mx - sc);
                l *= corr;
                unsigned long long c2 = pack2(corr);
                #pragma unroll
                for (int d = 0; d < 16; d++) {
                    mul2(a2[d], c2);
                }
                mx = sc;
            }
            float p = __expf(sc - mx);
            l += p;
            unsigned long long p2 = pack2(p);
            const ulonglong2* vp = (const ulonglong2*)vs[m];
            #pragma unroll
            for (int i = 0; i < 8; i++) {
                ulonglong2 va = vp[i];
                fma2(a2[2*i],   p2, va.x);
                fma2(a2[2*i+1], p2, va.y);
            }
        }
        __syncthreads();
    }

    float inv = 1.0f / l;
    #pragma unroll
    for (int j = 0; j < 8; j++) {
        float2 u0 = unpack2(a2[2*j]);
        float2 u1 = unpack2(a2[2*j+1]);
        float4 o = make_float4(u0.x*inv, u0.y*inv, u1.x*inv, u1.y*inv);
        split_store4(oh + qrow + 4*j, ol + qrow + 4*j, o);
    }
}

// ---------------- local window attention (R7) ----------------
__global__ void __launch_bounds__(128) lattn_kernel(
    const float* __restrict__ ql, const float* __restrict__ kvl,
    __nv_bfloat16* __restrict__ oh, __nv_bfloat16* __restrict__ ol)
{
    __shared__ float ks[2][49][HD];
    __shared__ float vs[2][49][HD];
    int bi = blockIdx.x;
    int hp = bi & 1;
    int wi = (bi >> 1) & 255;
    int b  = bi >> 9;
    int wy = wi >> 4;
    int wx = wi & 15;
    int tid = threadIdx.x;

    for (int i = tid; i < 2*49*8; i += 128) {
        int d4 = (i & 7) * 4;
        int t  = (i >> 3) % 49;
        int hh = i / (49*8);
        int py = t / WSZ;
        int px = t % WSZ;
        int n  = (wy*WSZ + py)*HW + wx*WSZ + px;
        size_t rowb = (size_t)(b*NTOK + n) * (2*LD) + (hp*2 + hh)*HD;
        *(float4*)&ks[hh][t][d4] = *(const float4*)&kvl[rowb + d4];
        *(float4*)&vs[hh][t][d4] = *(const float4*)&kvl[rowb + LD + d4];
    }
    __syncthreads();

    if (tid < 98) {
        int hh = tid / 49;
        int qi = tid % 49;
        int h  = hp*2 + hh;
        int py = qi / WSZ;
        int px = qi % WSZ;
        int n  = (wy*WSZ + py)*HW + wx*WSZ + px;
        size_t qrow = (size_t)(b*NTOK + n) * 256 + 128 + h*HD;

        unsigned long long q2[16];
        const ulonglong2* qp = (const ulonglong2*)&ql[qrow];
        #pragma unroll
        for (int j = 0; j < 8; j++) {
            ulonglong2 t = qp[j];
            q2[2*j]   = t.x;
            q2[2*j+1] = t.y;
        }

        float sc[49];
        float mx = -INFINITY;
        #pragma unroll
        for (int t = 0; t < 49; t++) {
            const ulonglong2* kp = (const ulonglong2*)ks[hh][t];
            unsigned long long s0 = 0ULL, s1 = 0ULL, s2 = 0ULL, s3 = 0ULL;
            #pragma unroll
            for (int i = 0; i < 4; i++) {
                ulonglong2 ka = kp[2*i];
                ulonglong2 kb = kp[2*i+1];
                fma2(s0, q2[4*i+0], ka.x);
                fma2(s1, q2[4*i+1], ka.y);
                fma2(s2, q2[4*i+2], kb.x);
                fma2(s3, q2[4*i+3], kb.y);
            }
            float2 f0 = unpack2(s0);
            float2 f1 = unpack2(s1);
            float2 f2 = unpack2(s2);
            float2 f3 = unpack2(s3);
            float s = ((f0.x + f0.y) + (f1.x + f1.y) + (f2.x + f2.y) + (f3.x + f3.y)) * ATT_SCALE;
            sc[t] = s;
            mx = fmaxf(mx, s);
        }
        float l = 0.0f;
        #pragma unroll
        for (int t = 0; t < 49; t++) {
            sc[t] = __expf(sc[t] - mx);
            l += sc[t];
        }
        float inv = 1.0f / l;

        unsigned long long a2[16];
        #pragma unroll
        for (int d = 0; d < 16; d++) {
            a2[d] = 0ULL;
        }
        #pragma unroll
        for (int t = 0; t < 49; t++) {
            unsigned long long p2 = pack2(sc[t] * inv);
            const ulonglong2* vp = (const ulonglong2*)vs[hh][t];
            #pragma unroll
            for (int i = 0; i < 8; i++) {
                ulonglong2 va = vp[i];
                fma2(a2[2*i],   p2, va.x);
                fma2(a2[2*i+1], p2, va.y);
            }
        }
        #pragma unroll
        for (int j = 0; j < 8; j++) {
            float2 u0 = unpack2(a2[2*j]);
            float2 u1 = unpack2(a2[2*j+1]);
            float4 o = make_float4(u0.x, u0.y, u1.x, u1.y);
            split_store4(oh + qrow + 4*j, ol + qrow + 4*j, o);
        }
    }
}

// ---------------- depthwise 3x3 conv + exact GELU, 4-row blocked (R7) --------
__device__ __forceinline__ float gelu_exact(float v)
{
    return 0.5f * v * (1.0f + erff(v * 0.70710678118654752f));
}

__global__ void dwconv_gelu_kernel(const float* __restrict__ h, const float* __restrict__ w,
                                   const float* __restrict__ bias,
                                   __nv_bfloat16* __restrict__ oh, __nv_bfloat16* __restrict__ ol)
{
    int t = blockIdx.x * blockDim.x + threadIdx.x;
    int c4 = t & 255;
    int rest = t >> 8;
    int xx = rest % HW;
    int tmp = rest / HW;
    int y4 = tmp % (HW/4);
    int bb = tmp / (HW/4);
    int yy0 = y4 * 4;
    int c  = c4 * 4;

    float wv[4][9];
    #pragma unroll
    for (int e = 0; e < 4; e++) {
        #pragma unroll
        for (int k = 0; k < 9; k++) {
            wv[e][k] = w[(c+e)*9 + k];
        }
    }

    float4 bz = *(const float4*)&bias[c];
    float4 acc[4];
    #pragma unroll
    for (int oy = 0; oy < 4; oy++) {
        acc[oy] = bz;
    }

    #pragma unroll
    for (int ry = 0; ry < 6; ry++) {
        int y2 = yy0 - 1 + ry;
        if ((unsigned)y2 >= HW) continue;
        #pragma unroll
        for (int dx = 0; dx < 3; dx++) {
            int x2 = xx + dx - 1;
            if ((unsigned)x2 >= HW) continue;
            float4 v = *(const float4*)&h[((size_t)bb*NTOK + y2*HW + x2) * HID + c];
            #pragma unroll
            for (int oy = 0; oy < 4; oy++) {
                int dy = ry - oy;
                if (dy < 0 || dy > 2) continue;
                int k = dy*3 + dx;
                acc[oy].x = fmaf(v.x, wv[0][k], acc[oy].x);
                acc[oy].y = fmaf(v.y, wv[1][k], acc[oy].y);
                acc[oy].z = fmaf(v.z, wv[2][k], acc[oy].z);
                acc[oy].w = fmaf(v.w, wv[3][k], acc[oy].w);
            }
        }
    }

    #pragma unroll
    for (int oy = 0; oy < 4; oy++) {
        float4 a = acc[oy];
        a.x = gelu_exact(a.x);
        a.y = gelu_exact(a.y);
        a.z = gelu_exact(a.z);
        a.w = gelu_exact(a.w);
        size_t off = ((size_t)bb*NTOK + (yy0+oy)*HW + xx) * HID + c;
        split_store4(oh + off, ol + off, a);
    }
}

// ---------------- persistent host objects (created once, reused) -------------
static cudaStream_t h_s1 = 0;
static cudaStream_t h_s2 = 0;
static cudaEvent_t  h_e_wt = 0, h_e_ln = 0, h_e_q = 0, h_e_gkv = 0, h_e_lp = 0, h_e_fork = 0;
static cudaEvent_t  h_e_f1a = 0, h_e_fc2a = 0;
static int h_objs_ready = 0;

// ---------------- launch (stream-parallel DAG inside graph capture) ----------
extern "C" void kernel_launch(void* const* d_in, const int* in_sizes, int n_in,
                              void* d_out, int out_size)
{
    const float* x     = (const float*)d_in[0];
    const float* xr    = (const float*)d_in[1];
    const float* g1    = (const float*)d_in[2];
    const float* b1    = (const float*)d_in[3];
    const float* g2    = (const float*)d_in[4];
    const float* b2    = (const float*)d_in[5];
    const float* Gq_w  = (const float*)d_in[6];
    const float* Gq_b  = (const float*)d_in[7];
    const float* Gkv_w = (const float*)d_in[8];
    const float* Gkv_b = (const float*)d_in[9];
    const float* Gp_w  = (const float*)d_in[10];
    const float* Gp_b  = (const float*)d_in[11];
    const float* Lq_w  = (const float*)d_in[12];
    const float* Lq_b  = (const float*)d_in[13];
    const float* Lkv_w = (const float*)d_in[14];
    const float* Lkv_b = (const float*)d_in[15];
    const float* Lp_w  = (const float*)d_in[16];
    const float* Lp_b  = (const float*)d_in[17];
    const float* fc1_w = (const float*)d_in[18];
    const float* fc1_b = (const float*)d_in[19];
    const float* dw_w  = (const float*)d_in[20];
    const float* dw_b  = (const float*)d_in[21];
    const float* fc2_w = (const float*)d_in[22];
    const float* fc2_b = (const float*)d_in[23];
    float* out = (float*)d_out;

    __nv_bfloat16 *p_xn_h;
    __nv_bfloat16 *p_xn_l;
    __nv_bfloat16 *p_xrn_h;
    __nv_bfloat16 *p_xrn_l;
    __nv_bfloat16 *p_pool_h;
    __nv_bfloat16 *p_pool_l;
    __nv_bfloat16 *p_att_h;
    __nv_bfloat16 *p_att_l;
    __nv_bfloat16 *p_ln2_h;
    __nv_bfloat16 *p_ln2_l;
    __nv_bfloat16 *p_h2_h;
    __nv_bfloat16 *p_h2_l;
    float *p_qq;
    float *p_kv;
    float *p_kvl;
    float *p_cat;
    float *p_h1;
    float *p_bq;
    __nv_bfloat16 *p_wq_h;
    __nv_bfloat16 *p_wq_l;
    __nv_bfloat16 *p_wkv_h;
    __nv_bfloat16 *p_wkv_l;
    __nv_bfloat16 *p_wlkv_h;
    __nv_bfloat16 *p_wlkv_l;
    __nv_bfloat16 *p_wgp_h;
    __nv_bfloat16 *p_wgp_l;
    __nv_bfloat16 *p_wlp_h;
    __nv_bfloat16 *p_wlp_l;
    __nv_bfloat16 *p_wfc1_h;
    __nv_bfloat16 *p_wfc1_l;
    __nv_bfloat16 *p_wfc2_h;
    __nv_bfloat16 *p_wfc2_l;

    cudaGetSymbolAddress((void**)&p_xn_h, g_xn_h);
    cudaGetSymbolAddress((void**)&p_xn_l, g_xn_l);
    cudaGetSymbolAddress((void**)&p_xrn_h, g_xrn_h);
    cudaGetSymbolAddress((void**)&p_xrn_l, g_xrn_l);
    cudaGetSymbolAddress((void**)&p_pool_h, g_pool_h);
    cudaGetSymbolAddress((void**)&p_pool_l, g_pool_l);
    cudaGetSymbolAddress((void**)&p_att_h, g_att_h);
    cudaGetSymbolAddress((void**)&p_att_l, g_att_l);
    cudaGetSymbolAddress((void**)&p_ln2_h, g_ln2_h);
    cudaGetSymbolAddress((void**)&p_ln2_l, g_ln2_l);
    cudaGetSymbolAddress((void**)&p_h2_h, g_h2_h);
    cudaGetSymbolAddress((void**)&p_h2_l, g_h2_l);
    cudaGetSymbolAddress((void**)&p_qq, g_qq);
    cudaGetSymbolAddress((void**)&p_kv, g_kv);
    cudaGetSymbolAddress((void**)&p_kvl, g_kvl);
    cudaGetSymbolAddress((void**)&p_cat, g_cat);
    cudaGetSymbolAddress((void**)&p_h1, g_h1);
    cudaGetSymbolAddress((void**)&p_bq, b_q);
    cudaGetSymbolAddress((void**)&p_wq_h, w_q_h);
    cudaGetSymbolAddress((void**)&p_wq_l, w_q_l);
    cudaGetSymbolAddress((void**)&p_wkv_h, w_kv_h);
    cudaGetSymbolAddress((void**)&p_wkv_l, w_kv_l);
    cudaGetSymbolAddress((void**)&p_wlkv_h, w_lkv_h);
    cudaGetSymbolAddress((void**)&p_wlkv_l, w_lkv_l);
    cudaGetSymbolAddress((void**)&p_wgp_h, w_gp_h);
    cudaGetSymbolAddress((void**)&p_wgp_l, w_gp_l);
    cudaGetSymbolAddress((void**)&p_wlp_h, w_lp_h);
    cudaGetSymbolAddress((void**)&p_wlp_l, w_lp_l);
    cudaGetSymbolAddress((void**)&p_wfc1_h, w_fc1_h);
    cudaGetSymbolAddress((void**)&p_wfc1_l, w_fc1_l);
    cudaGetSymbolAddress((void**)&p_wfc2_h, w_fc2_h);
    cudaGetSymbolAddress((void**)&p_wfc2_l, w_fc2_l);

    const int SMEM = 2 * 4 * TILEB * (int)sizeof(__nv_bfloat16);   // 81920
    cudaFuncSetAttribute(mma_gemm, cudaFuncAttributeMaxDynamicSharedMemorySize, SMEM);

    if (!h_objs_ready) {
        cudaStreamCreateWithFlags(&h_s1, cudaStreamNonBlocking);
        cudaStreamCreateWithFlags(&h_s2, cudaStreamNonBlocking);
        cudaEventCreateWithFlags(&h_e_wt,   cudaEventDisableTiming);
        cudaEventCreateWithFlags(&h_e_ln,   cudaEventDisableTiming);
        cudaEventCreateWithFlags(&h_e_q,    cudaEventDisableTiming);
        cudaEventCreateWithFlags(&h_e_gkv,  cudaEventDisableTiming);
        cudaEventCreateWithFlags(&h_e_lp,   cudaEventDisableTiming);
        cudaEventCreateWithFlags(&h_e_fork, cudaEventDisableTiming);
        cudaEventCreateWithFlags(&h_e_f1a,  cudaEventDisableTiming);
        cudaEventCreateWithFlags(&h_e_fc2a, cudaEventDisableTiming);
        h_objs_ready = 1;
    }
    cudaStream_t s1 = h_s1;
    cudaStream_t s2 = h_s2;

    // fork s1/s2 off the capture stream so they join the capture
    cudaEventRecord(h_e_fork, 0);
    cudaStreamWaitEvent(s1, h_e_fork, 0);
    cudaStreamWaitEvent(s2, h_e_fork, 0);

    // s1: weight transpose (independent of LN)
    wtrans_all<<<2945, 256, 0, s1>>>(Gq_w, Gkv_w, Gp_w, Lq_w, Lkv_w, Lp_w,
                                     fc1_w, fc2_w, Gq_b, Lq_b);
    cudaEventRecord(h_e_wt, s1);

    // s0: both LayerNorms
    ln_kernel<<<ROWS/8, 256>>>(x,  g1, b1, p_xn_h,  p_xn_l,  ROWS);
    ln_kernel<<<ROWS/8, 256>>>(xr, g1, b1, p_xrn_h, p_xrn_l, ROWS);
    cudaEventRecord(h_e_ln, 0);

    // s0: Q projection (needs ln(x) + weights)
    cudaStreamWaitEvent(0, h_e_wt, 0);
    mma_gemm<<<dim3(2, ROWS/128), 256, SMEM>>>(p_xn_h, p_xn_l, p_wq_h, p_wq_l, p_bq, 0,
                                               p_qq, ROWS, 256, CDIM, CDIM, 256, 0);
    cudaEventRecord(h_e_q, 0);

    // s2: pool -> Gkv (needs ln(xr) + weights)
    cudaStreamWaitEvent(s2, h_e_ln, 0);
    cudaStreamWaitEvent(s2, h_e_wt, 0);
    pool_kernel<<<(BATCH*MPOOL*CDIM)/256, 256, 0, s2>>>(p_xrn_h, p_xrn_l, p_pool_h, p_pool_l);
    mma_gemm<<<dim3(2, (BATCH*MPOOL)/128), 256, SMEM, s2>>>(p_pool_h, p_pool_l, p_wkv_h, p_wkv_l, Gkv_b, 0,
                                               p_kv, BATCH*MPOOL, 2*GD, CDIM, CDIM, 2*GD, 0);
    cudaEventRecord(h_e_gkv, s2);

    // s1: Lkv projection (needs ln(xr); weights already on s1)
    cudaStreamWaitEvent(s1, h_e_ln, 0);
    mma_gemm<<<dim3(2, ROWS/128), 256, SMEM, s1>>>(p_xrn_h, p_xrn_l, p_wlkv_h, p_wlkv_l, Lkv_b, 0,
                                               p_kvl, ROWS, 2*LD, CDIM, CDIM, 2*LD, 0);

    // s0: global attention (needs Q on s0, Gkv on s2)
    cudaStreamWaitEvent(0, h_e_gkv, 0);
    gattn_kernel<<<BATCH*GH*(NTOK/128), 128>>>(p_qq, p_kv, p_att_h, p_att_l);
    // s0: Gp projection
    mma_gemm<<<dim3(1, ROWS/128), 256, SMEM>>>(p_att_h, p_att_l, p_wgp_h, p_wgp_l, Gp_b, 0,
                                               p_cat, ROWS, GD, GD, 256, CDIM, 0);

    // s1: local attention (needs Q via e_q; Lkv on s1) then Lp
    cudaStreamWaitEvent(s1, h_e_q, 0);
    lattn_kernel<<<BATCH*256*2, 128, 0, s1>>>(p_qq, p_kvl, p_att_h, p_att_l);
    mma_gemm<<<dim3(1, ROWS/128), 256, SMEM, s1>>>(p_att_h + 128, p_att_l + 128, p_wlp_h, p_wlp_l, Lp_b, 0,
                                               p_cat, ROWS, LD, LD, 256, CDIM, GD);
    cudaEventRecord(h_e_lp, s1);

    // s0: join Lp, then fused residual add + ln2
    cudaStreamWaitEvent(0, h_e_lp, 0);
    addln_kernel<<<ROWS/8, 256>>>(x, p_cat, g2, b2, out, p_ln2_h, p_ln2_l);

    // -------- pipelined MLP tail: batch halves (rows [0,HALFR) / [HALFR,ROWS)) ----
    const size_t offA1 = (size_t)HALFR * CDIM;   // ln2 / out offset (elements)
    const size_t offH  = (size_t)HALFR * HID;    // h1 / h2 offset

    // s0: FC1 half A, then FC1 half B (sequential on s0 to stagger)
    mma_gemm<<<dim3(8, HALFR/128), 256, SMEM>>>(p_ln2_h, p_ln2_l, p_wfc1_h, p_wfc1_l, fc1_b, 0,
                                                p_h1, HALFR, HID, CDIM, CDIM, HID, 0);
    cudaEventRecord(h_e_f1a, 0);
    mma_gemm<<<dim3(8, HALFR/128), 256, SMEM>>>(p_ln2_h + offA1, p_ln2_l + offA1, p_wfc1_h, p_wfc1_l, fc1_b, 0,
                                                p_h1 + offH, HALFR, HID, CDIM, CDIM, HID, 0);

    // s1: dwconv + FC2 for half A (overlaps FC1 half B on s0)
    cudaStreamWaitEvent(s1, h_e_f1a, 0);
    dwconv_gelu_kernel<<<(2*(HW/4)*HW*256)/256, 256, 0, s1>>>(p_h1, dw_w, dw_b, p_h2_h, p_h2_l);
    mma_gemm<<<dim3(2, HALFR/128), 256, SMEM, s1>>>(p_h2_h, p_h2_l, p_wfc2_h, p_wfc2_l, fc2_b, out,
                                                    out, HALFR, CDIM, HID, HID, CDIM, 0);
    cudaEventRecord(h_e_fc2a, s1);

    // s0: dwconv + FC2 for half B (overlaps FC2 half A on s1)
    dwconv_gelu_kernel<<<(2*(HW/4)*HW*256)/256, 256>>>(p_h1 + offH, dw_w, dw_b,
                                                       p_h2_h + offH, p_h2_l + offH);
    mma_gemm<<<dim3(2, HALFR/128), 256, SMEM>>>(p_h2_h + offH, p_h2_l + offH, p_wfc2_h, p_wfc2_l, fc2_b,
                                                out + offA1, out + offA1, HALFR, CDIM, HID, HID, CDIM, 0);

    // join half A back to s0
    cudaStreamWaitEvent(0, h_e_fc2a, 0);
}

// round 15
// speedup vs baseline: 1.2094x; 1.2094x over previous
#include <cuda_runtime.h>
#include <cuda_bf16.h>
#include <math.h>

// ---------------- problem constants ----------------
#define BATCH 4
#define HW    112
#define NTOK  12544
#define CDIM  256
#define GH    4
#define HD    32
#define GD    128
#define LD    128
#define HID   1024
#define WSZ   7
#define MPOOL 256
#define ROWS  (BATCH*NTOK)
#define ATT_SCALE 0.17677669529663687f

#define PADK  40
#define TILEB (128*PADK)
#define STG   (3*TILEB)          // stage stride: A-hi, B-hi, B-lo

// ---------------- scratch (device globals; no allocation) ----------------
__device__ __align__(256) __nv_bfloat16 g_xn  [ROWS*CDIM];
__device__ __align__(256) __nv_bfloat16 g_xrn [ROWS*CDIM];
__device__ __align__(256) __nv_bfloat16 g_pool[BATCH*MPOOL*CDIM];
__device__ __align__(256) float g_qq [ROWS*256];         // [Gq | Lq]
__device__ __align__(256) float g_kv [BATCH*MPOOL*2*GD];
__device__ __align__(256) float g_kvl[ROWS*2*LD];
__device__ __align__(256) __nv_bfloat16 g_att[ROWS*256];  // [gattn | lattn]
__device__ __align__(256) float g_cat[ROWS*CDIM];
__device__ __align__(256) __nv_bfloat16 g_ln2[ROWS*CDIM];
__device__ __align__(256) float g_h1 [ROWS*HID];
__device__ __align__(256) __nv_bfloat16 g_h2 [ROWS*HID];
// transposed split weights [N][K] + merged bias
__device__ __align__(256) __nv_bfloat16 w_q_h [256*CDIM];
__device__ __align__(256) __nv_bfloat16 w_q_l [256*CDIM];
__device__ __align__(256) __nv_bfloat16 w_kv_h[256*CDIM];
__device__ __align__(256) __nv_bfloat16 w_kv_l[256*CDIM];
__device__ __align__(256) __nv_bfloat16 w_lkv_h[256*CDIM];
__device__ __align__(256) __nv_bfloat16 w_lkv_l[256*CDIM];
__device__ __align__(256) __nv_bfloat16 w_gp_h [GD*GD];
__device__ __align__(256) __nv_bfloat16 w_gp_l [GD*GD];
__device__ __align__(256) __nv_bfloat16 w_lp_h [LD*LD];
__device__ __align__(256) __nv_bfloat16 w_lp_l [LD*LD];
__device__ __align__(256) __nv_bfloat16 w_fc1_h[HID*CDIM];
__device__ __align__(256) __nv_bfloat16 w_fc1_l[HID*CDIM];
__device__ __align__(256) __nv_bfloat16 w_fc2_h[CDIM*HID];
__device__ __align__(256) __nv_bfloat16 w_fc2_l[CDIM*HID];
__device__ __align__(256) float b_q[256];

// ---------------- helpers ----------------
__device__ __forceinline__ void bf16_store4(__nv_bfloat16* p, float4 v)
{
    __nv_bfloat162 h0 = __nv_bfloat162(__float2bfloat16(v.x), __float2bfloat16(v.y));
    __nv_bfloat162 h1 = __nv_bfloat162(__float2bfloat16(v.z), __float2bfloat16(v.w));
    ((__nv_bfloat162*)p)[0] = h0;
    ((__nv_bfloat162*)p)[1] = h1;
}

__device__ __forceinline__ unsigned smem_u32(const void* p)
{
    return (unsigned)__cvta_generic_to_shared(p);
}

__device__ __forceinline__ void ldsm4(unsigned* r, unsigned addr)
{
    asm volatile("ldmatrix.sync.aligned.m8n8.x4.shared.b16 {%0,%1,%2,%3}, [%4];"
        : "=r"(r[0]), "=r"(r[1]), "=r"(r[2]), "=r"(r[3]) : "r"(addr));
}

__device__ __forceinline__ void mma_bf16(float* c, const unsigned* a, const unsigned* b)
{
    asm volatile("mma.sync.aligned.m16n8k16.row.col.f32.bf16.bf16.f32 "
        "{%0,%1,%2,%3},{%4,%5,%6,%7},{%8,%9},{%0,%1,%2,%3};"
        : "+f"(c[0]), "+f"(c[1]), "+f"(c[2]), "+f"(c[3])
        : "r"(a[0]), "r"(a[1]), "r"(a[2]), "r"(a[3]), "r"(b[0]), "r"(b[1]));
}

__device__ __forceinline__ void cpa16(unsigned saddr, const void* g)
{
    asm volatile("cp.async.cg.shared.global [%0], [%1], 16;" :: "r"(saddr), "l"(g) : "memory");
}

// ---- packed f32x2 math ----
__device__ __forceinline__ void fma2(unsigned long long& d, unsigned long long a,
                                     unsigned long long b)
{
    asm("fma.rn.f32x2 %0, %1, %2, %0;" : "+l"(d) : "l"(a), "l"(b));
}

__device__ __forceinline__ void mul2(unsigned long long& d, unsigned long long c)
{
    asm("mul.rn.f32x2 %0, %0, %1;" : "+l"(d) : "l"(c));
}

__device__ __forceinline__ unsigned long long pack2(float x)
{
    unsigned long long r;
    asm("mov.b64 %0, {%1, %1};" : "=l"(r) : "f"(x));
    return r;
}

__device__ __forceinline__ float2 unpack2(unsigned long long v)
{
    float2 f;
    asm("mov.b64 {%0, %1}, %2;" : "=f"(f.x), "=f"(f.y) : "l"(v));
    return f;
}

// stage loader: 256 threads, 3 tiles (A-hi, B-hi, B-lo) x 512 16B-chunks
__device__ __forceinline__ void gemm_stage(
    __nv_bfloat16* sbase, int tid,
    const __nv_bfloat16* Ah,
    const __nv_bfloat16* Bh, const __nv_bfloat16* Bl,
    int bm, int bn, int K, int lda, int k0)
{
    __nv_bfloat16* sA  = sbase;
    __nv_bfloat16* sB0 = sbase + TILEB;
    __nv_bfloat16* sB1 = sbase + 2*TILEB;
    #pragma unroll
    for (int j = 0; j < 2; j++) {
        int u = tid + 256*j;
        int row = u >> 2;
        int qq = u & 3;
        int so = row * PADK + qq * 8;
        size_t gA = (size_t)(bm + row) * lda + k0 + qq * 8;
        size_t gB = (size_t)(bn + row) * K + k0 + qq * 8;
        cpa16(smem_u32(sA  + so), Ah + gA);
        cpa16(smem_u32(sB0 + so), Bh + gB);
        cpa16(smem_u32(sB1 + so), Bl + gB);
    }
}

// ---------------- single-launch weight transpose + split ----------------
__device__ __forceinline__ void wt_store(__nv_bfloat16* hi, __nv_bfloat16* lo,
                                         int t, float v)
{
    __nv_bfloat16 h = __float2bfloat16(v);
    hi[t] = h;
    lo[t] = __float2bfloat16(v - __bfloat162float(h));
}

__global__ void wtrans_all(const float* __restrict__ Gq, const float* __restrict__ Gkv,
                           const float* __restrict__ Gp, const float* __restrict__ Lq,
                           const float* __restrict__ Lkv, const float* __restrict__ Lp,
                           const float* __restrict__ fc1, const float* __restrict__ fc2,
                           const float* __restrict__ Gq_b, const float* __restrict__ Lq_b)
{
    int t = blockIdx.x * blockDim.x + threadIdx.x;
    if (t < 65536) {
        int n = t >> 8;
        int k = t & 255;
        float v = (n < 128) ? Gq[(size_t)k*128 + n] : Lq[(size_t)k*128 + (n-128)];
        wt_store(w_q_h, w_q_l, t, v);
    } else if (t < 131072) {
        int u = t - 65536;
        int n = u >> 8;
        int k = u & 255;
        wt_store(w_kv_h, w_kv_l, u, Gkv[(size_t)k*256 + n]);
    } else if (t < 196608) {
        int u = t - 131072;
        int n = u >> 8;
        int k = u & 255;
        wt_store(w_lkv_h, w_lkv_l, u, Lkv[(size_t)k*256 + n]);
    } else if (t < 212992) {
        int u = t - 196608;
        int n = u >> 7;
        int k = u & 127;
        wt_store(w_gp_h, w_gp_l, u, Gp[(size_t)k*128 + n]);
    } else if (t < 229376) {
        int u = t - 212992;
        int n = u >> 7;
        int k = u & 127;
        wt_store(w_lp_h, w_lp_l, u, Lp[(size_t)k*128 + n]);
    } else if (t < 491520) {
        int u = t - 229376;
        int n = u >> 8;
        int k = u & 255;
        wt_store(w_fc1_h, w_fc1_l, u, fc1[(size_t)k*1024 + n]);
    } else if (t < 753664) {
        int u = t - 491520;
        int n = u / 1024;
        int k = u - n * 1024;
        wt_store(w_fc2_h, w_fc2_l, u, fc2[(size_t)k*256 + n]);
    } else if (t < 753920) {
        int u = t - 753664;
        b_q[u] = (u < 128) ? Gq_b[u] : Lq_b[u-128];
    }
}

// ---------------- LayerNorm (ln1, bf16 out) ----------------
__global__ void ln_kernel(const float* __restrict__ x, const float* __restrict__ g,
                          const float* __restrict__ b,
                          __nv_bfloat16* __restrict__ oh, int rows)
{
    int gw   = (blockIdx.x * blockDim.x + threadIdx.x) >> 5;
    int lane = threadIdx.x & 31;
    if (gw >= rows) return;
    const float4* xr = (const float4*)(x + (size_t)gw * CDIM);
    float4 v0 = xr[lane];
    float4 v1 = xr[lane + 32];
    float s  = v0.x+v0.y+v0.z+v0.w + v1.x+v1.y+v1.z+v1.w;
    float ss = v0.x*v0.x+v0.y*v0.y+v0.z*v0.z+v0.w*v0.w
             + v1.x*v1.x+v1.y*v1.y+v1.z*v1.z+v1.w*v1.w;
    #pragma unroll
    for (int o = 16; o; o >>= 1) {
        s  += __shfl_xor_sync(0xffffffffu, s,  o);
        ss += __shfl_xor_sync(0xffffffffu, ss, o);
    }
    float mean = s * (1.0f/CDIM);
    float var  = ss * (1.0f/CDIM) - mean*mean;
    float inv  = rsqrtf(var + 1e-5f);
    const float4* g4 = (const float4*)g;
    const float4* b4 = (const float4*)b;
    float4 G0 = g4[lane];
    float4 B0 = b4[lane];
    float4 G1 = g4[lane+32];
    float4 B1 = b4[lane+32];
    float4 o0, o1;
    o0.x = (v0.x-mean)*inv*G0.x + B0.x;
    o0.y = (v0.y-mean)*inv*G0.y + B0.y;
    o0.z = (v0.z-mean)*inv*G0.z + B0.z;
    o0.w = (v0.w-mean)*inv*G0.w + B0.w;
    o1.x = (v1.x-mean)*inv*G1.x + B1.x;
    o1.y = (v1.y-mean)*inv*G1.y + B1.y;
    o1.z = (v1.z-mean)*inv*G1.z + B1.z;
    o1.w = (v1.w-mean)*inv*G1.w + B1.w;
    size_t base = (size_t)gw * CDIM + lane * 4;
    bf16_store4(oh + base,       o0);
    bf16_store4(oh + base + 128, o1);
}

// ---------------- fused residual add + LayerNorm (ln2, bf16 out) -------------
__global__ void addln_kernel(const float* __restrict__ x, const float* __restrict__ cat,
                             const float* __restrict__ g, const float* __restrict__ b,
                             float* __restrict__ out, __nv_bfloat16* __restrict__ oh)
{
    int gw   = (blockIdx.x * blockDim.x + threadIdx.x) >> 5;
    int lane = threadIdx.x & 31;
    const float4* xr = (const float4*)(x + (size_t)gw * CDIM);
    const float4* cr = (const float4*)(cat + (size_t)gw * CDIM);
    float4 a0 = xr[lane];
    float4 a1 = xr[lane + 32];
    float4 c0 = cr[lane];
    float4 c1 = cr[lane + 32];
    float4 v0 = make_float4(a0.x+c0.x, a0.y+c0.y, a0.z+c0.z, a0.w+c0.w);
    float4 v1 = make_float4(a1.x+c1.x, a1.y+c1.y, a1.z+c1.z, a1.w+c1.w);
    float4* orow = (float4*)(out + (size_t)gw * CDIM);
    orow[lane]      = v0;
    orow[lane + 32] = v1;
    float s  = v0.x+v0.y+v0.z+v0.w + v1.x+v1.y+v1.z+v1.w;
    float ss = v0.x*v0.x+v0.y*v0.y+v0.z*v0.z+v0.w*v0.w
             + v1.x*v1.x+v1.y*v1.y+v1.z*v1.z+v1.w*v1.w;
    #pragma unroll
    for (int o = 16; o; o >>= 1) {
        s  += __shfl_xor_sync(0xffffffffu, s,  o);
        ss += __shfl_xor_sync(0xffffffffu, ss, o);
    }
    float mean = s * (1.0f/CDIM);
    float var  = ss * (1.0f/CDIM) - mean*mean;
    float inv  = rsqrtf(var + 1e-5f);
    const float4* g4 = (const float4*)g;
    const float4* b4 = (const float4*)b;
    float4 G0 = g4[lane];
    float4 B0 = b4[lane];
    float4 G1 = g4[lane+32];
    float4 B1 = b4[lane+32];
    float4 o0, o1;
    o0.x = (v0.x-mean)*inv*G0.x + B0.x;
    o0.y = (v0.y-mean)*inv*G0.y + B0.y;
    o0.z = (v0.z-mean)*inv*G0.z + B0.z;
    o0.w = (v0.w-mean)*inv*G0.w + B0.w;
    o1.x = (v1.x-mean)*inv*G1.x + B1.x;
    o1.y = (v1.y-mean)*inv*G1.y + B1.y;
    o1.z = (v1.z-mean)*inv*G1.z + B1.z;
    o1.w = (v1.w-mean)*inv*G1.w + B1.w;
    size_t base = (size_t)gw * CDIM + lane * 4;
    bf16_store4(oh + base,       o0);
    bf16_store4(oh + base + 128, o1);
}

// ---------------- 7x7 mean pooling (bf16 in/out) ----------------
__global__ void pool_kernel(const __nv_bfloat16* __restrict__ xh,
                            __nv_bfloat16* __restrict__ ph)
{
    int t = blockIdx.x * blockDim.x + threadIdx.x;
    int c = t & 255;
    int g = (t >> 8) & 255;
    int b = t >> 16;
    int gy = g >> 4;
    int gx = g & 15;
    float s = 0.0f;
    #pragma unroll
    for (int py = 0; py < WSZ; py++) {
        int rowbase = (gy*WSZ + py) * HW + gx*WSZ;
        #pragma unroll
        for (int px = 0; px < WSZ; px++) {
            size_t idx = ((size_t)b*NTOK + rowbase + px) * CDIM + c;
            s += __bfloat162float(xh[idx]);
        }
    }
    ph[t] = __float2bfloat16(s * (1.0f/49.0f));
}

// ---------------- tensor-core bf16x2 GEMM: A-hi x (B-hi + B-lo) --------------
// C[m, coff+n] = (addsrc?) + Ah[M,K](lda) @ (Bh+Bl)[N,K]^T + bias[n]
__global__ void __launch_bounds__(256, 2) mma_gemm(
    const __nv_bfloat16* __restrict__ Ah,
    const __nv_bfloat16* __restrict__ Bh, const __nv_bfloat16* __restrict__ Bl,
    const float* __restrict__ bias, const float* __restrict__ addsrc,
    float* __restrict__ C, int M, int N, int K, int lda, int ldc, int coff)
{
    extern __shared__ __nv_bfloat16 sh[];
    int tid  = threadIdx.x;
    int lane = tid & 31;
    int warp = tid >> 5;
    int wm = (warp & 3) * 32;
    int wn = (warp >> 2) * 64;
    int bm = blockIdx.y * 128;
    int bn = blockIdx.x * 128;

    float acc[2][8][4];
    #pragma unroll
    for (int i = 0; i < 2; i++) {
        #pragma unroll
        for (int j = 0; j < 8; j++) {
            #pragma unroll
            for (int e = 0; e < 4; e++) {
                acc[i][j][e] = 0.0f;
            }
        }
    }

    int nIter = K >> 5;

    gemm_stage(sh, tid, Ah, Bh, Bl, bm, bn, K, lda, 0);
    asm volatile("cp.async.commit_group;" ::: "memory");

    for (int it = 0; it < nIter; it++) {
        int st = it & 1;
        if (it + 1 < nIter) {
            gemm_stage(sh + (st^1)*STG, tid, Ah, Bh, Bl, bm, bn, K, lda, (it+1) << 5);
            asm volatile("cp.async.commit_group;" ::: "memory");
            asm volatile("cp.async.wait_group 1;" ::: "memory");
        } else {
            asm volatile("cp.async.wait_group 0;" ::: "memory");
        }
        __syncthreads();

        const __nv_bfloat16* cA  = sh + st*STG;
        const __nv_bfloat16* cB0 = cA + TILEB;
        const __nv_bfloat16* cB1 = cA + 2*TILEB;

        #pragma unroll
        for (int kk = 0; kk < 2; kk++) {
            unsigned afh[2][4];
            #pragma unroll
            for (int mi = 0; mi < 2; mi++) {
                int row = wm + mi*16 + (lane & 15);
                int col = kk*16 + (lane >> 4) * 8;
                ldsm4(afh[mi], smem_u32(cA + row*PADK + col));
            }
            #pragma unroll
            for (int np = 0; np < 4; np++) {
                unsigned bfh[4];
                unsigned bfl[4];
                int row = wn + np*16 + (lane >> 4) * 8 + (lane & 7);
                int col = kk*16 + ((lane >> 3) & 1) * 8;
                ldsm4(bfh, smem_u32(cB0 + row*PADK + col));
                ldsm4(bfl, smem_u32(cB1 + row*PADK + col));
                #pragma unroll
                for (int mi = 0; mi < 2; mi++) {
                    mma_bf16(acc[mi][2*np],   afh[mi], &bfh[0]);
                    mma_bf16(acc[mi][2*np+1], afh[mi], &bfh[2]);
                    mma_bf16(acc[mi][2*np],   afh[mi], &bfl[0]);
                    mma_bf16(acc[mi][2*np+1], afh[mi], &bfl[2]);
                }
            }
        }
        __syncthreads();
    }

    int gg = lane >> 2;
    int t2 = (lane & 3) * 2;
    #pragma unroll
    for (int mi = 0; mi < 2; mi++) {
        #pragma unroll
        for (int half = 0; half < 2; half++) {
            int row = bm + wm + mi*16 + gg + half*8;
            #pragma unroll
            for (int ni = 0; ni < 8; ni++) {
                int col = bn + wn + ni*8 + t2;
                float2 bv = *(const float2*)&bias[col];
                float v0 = acc[mi][ni][half*2 + 0] + bv.x;
                float v1 = acc[mi][ni][half*2 + 1] + bv.y;
                size_t off = (size_t)row * ldc + coff + col;
                if (addsrc) {
                    float2 sv = *(const float2*)&addsrc[off];
                    v0 += sv.x;
                    v1 += sv.y;
                }
                *(float2*)&C[off] = make_float2(v0, v1);
            }
        }
    }
}

// ---------------- global attention (f32x2, bf16 out) ----------------
__global__ void __launch_bounds__(128) gattn_kernel(
    const float* __restrict__ q, const float* __restrict__ kv,
    __nv_bfloat16* __restrict__ oh)
{
    __shared__ float ks[128][HD];
    __shared__ float vs[128][HD];
    int bi = blockIdx.x;
    int qc = bi % (NTOK/128);
    int h  = (bi / (NTOK/128)) & (GH-1);
    int b  = bi / ((NTOK/128) * GH);
    int tid = threadIdx.x;
    int n   = qc*128 + tid;
    size_t qrow = (size_t)(b*NTOK + n) * 256 + h*HD;

    unsigned long long q2[16];
    {
        const ulonglong2* qp = (const ulonglong2*)&q[qrow];
        #pragma unroll
        for (int j = 0; j < 8; j++) {
            ulonglong2 t = qp[j];
            q2[2*j]   = t.x;
            q2[2*j+1] = t.y;
        }
    }

    float mx = -INFINITY;
    float l = 0.0f;
    unsigned long long a2[16];
    #pragma unroll
    for (int d = 0; d < 16; d++) {
        a2[d] = 0ULL;
    }

    for (int ch = 0; ch < 2; ch++) {
        #pragma unroll
        for (int j = 0; j < 8; j++) {
            int f4 = tid + 128*j;
            int m  = f4 >> 3;
            int d4 = (f4 & 7) * 4;
            size_t kvrow = (size_t)(b*MPOOL + ch*128 + m) * (2*GD) + h*HD;
            *(float4*)&ks[m][d4] = *(const float4*)&kv[kvrow + d4];
            *(float4*)&vs[m][d4] = *(const float4*)&kv[kvrow + GD + d4];
        }
        __syncthreads();
        for (int m = 0; m < 128; m++) {
            const ulonglong2* kp = (const ulonglong2*)ks[m];
            unsigned long long s0 = 0ULL, s1 = 0ULL, s2 = 0ULL, s3 = 0ULL;
            #pragma unroll
            for (int i = 0; i < 4; i++) {
                ulonglong2 ka = kp[2*i];
                ulonglong2 kb = kp[2*i+1];
                fma2(s0, q2[4*i+0], ka.x);
                fma2(s1, q2[4*i+1], ka.y);
                fma2(s2, q2[4*i+2], kb.x);
                fma2(s3, q2[4*i+3], kb.y);
            }
            float2 f0 = unpack2(s0);
            float2 f1 = unpack2(s1);
            float2 f2 = unpack2(s2);
            float2 f3 = unpack2(s3);
            float sdot = (f0.x + f0.y) + (f1.x + f1.y) + (f2.x + f2.y) + (f3.x + f3.y);
            float sc = sdot * ATT_SCALE;
            if (sc > mx) {
                float corr = __expf(mx - sc);
                l *= corr;
                unsigned long long c2 = pack2(corr);
                #pragma unroll
                for (int d = 0; d < 16; d++) {
                    mul2(a2[d], c2);
                }
                mx = sc;
            }
            float p = __expf(sc - mx);
            l += p;
            unsigned long long p2 = pack2(p);
            const ulonglong2* vp = (const ulonglong2*)vs[m];
            #pragma unroll
            for (int i = 0; i < 8; i++) {
                ulonglong2 va = vp[i];
                fma2(a2[2*i],   p2, va.x);
                fma2(a2[2*i+1], p2, va.y);
            }
        }
        __syncthreads();
    }

    float inv = 1.0f / l;
    #pragma unroll
    for (int j = 0; j < 8; j++) {
        float2 u0 = unpack2(a2[2*j]);
        float2 u1 = unpack2(a2[2*j+1]);
        bf16_store4(oh + qrow + 4*j, make_float4(u0.x*inv, u0.y*inv, u1.x*inv, u1.y*inv));
    }
}

// ---------------- local window attention (f32x2, bf16 out) ----------------
__global__ void __launch_bounds__(128) lattn_kernel(
    const float* __restrict__ ql, const float* __restrict__ kvl,
    __nv_bfloat16* __restrict__ oh)
{
    __shared__ float ks[2][49][HD];
    __shared__ float vs[2][49][HD];
    int bi = blockIdx.x;
    int hp = bi & 1;
    int wi = (bi >> 1) & 255;
    int b  = bi >> 9;
    int wy = wi >> 4;
    int wx = wi & 15;
    int tid = threadIdx.x;

    for (int i = tid; i < 2*49*8; i += 128) {
        int d4 = (i & 7) * 4;
        int t  = (i >> 3) % 49;
        int hh = i / (49*8);
        int py = t / WSZ;
        int px = t % WSZ;
        int n  = (wy*WSZ + py)*HW + wx*WSZ + px;
        size_t rowb = (size_t)(b*NTOK + n) * (2*LD) + (hp*2 + hh)*HD;
        *(float4*)&ks[hh][t][d4] = *(const float4*)&kvl[rowb + d4];
        *(float4*)&vs[hh][t][d4] = *(const float4*)&kvl[rowb + LD + d4];
    }
    __syncthreads();

    if (tid < 98) {
        int hh = tid / 49;
        int qi = tid % 49;
        int h  = hp*2 + hh;
        int py = qi / WSZ;
        int px = qi % WSZ;
        int n  = (wy*WSZ + py)*HW + wx*WSZ + px;
        size_t qrow = (size_t)(b*NTOK + n) * 256 + 128 + h*HD;

        unsigned long long q2[16];
        const ulonglong2* qp = (const ulonglong2*)&ql[qrow];
        #pragma unroll
        for (int j = 0; j < 8; j++) {
            ulonglong2 t = qp[j];
            q2[2*j]   = t.x;
            q2[2*j+1] = t.y;
        }

        float sc[49];
        float mx = -INFINITY;
        #pragma unroll
        for (int t = 0; t < 49; t++) {
            const ulonglong2* kp = (const ulonglong2*)ks[hh][t];
            unsigned long long s0 = 0ULL, s1 = 0ULL, s2 = 0ULL, s3 = 0ULL;
            #pragma unroll
            for (int i = 0; i < 4; i++) {
                ulonglong2 ka = kp[2*i];
                ulonglong2 kb = kp[2*i+1];
                fma2(s0, q2[4*i+0], ka.x);
                fma2(s1, q2[4*i+1], ka.y);
                fma2(s2, q2[4*i+2], kb.x);
                fma2(s3, q2[4*i+3], kb.y);
            }
            float2 f0 = unpack2(s0);
            float2 f1 = unpack2(s1);
            float2 f2 = unpack2(s2);
            float2 f3 = unpack2(s3);
            float s = ((f0.x + f0.y) + (f1.x + f1.y) + (f2.x + f2.y) + (f3.x + f3.y)) * ATT_SCALE;
            sc[t] = s;
            mx = fmaxf(mx, s);
        }
        float l = 0.0f;
        #pragma unroll
        for (int t = 0; t < 49; t++) {
            sc[t] = __expf(sc[t] - mx);
            l += sc[t];
        }
        float inv = 1.0f / l;

        unsigned long long a2[16];
        #pragma unroll
        for (int d = 0; d < 16; d++) {
            a2[d] = 0ULL;
        }
        #pragma unroll
        for (int t = 0; t < 49; t++) {
            unsigned long long p2 = pack2(sc[t] * inv);
            const ulonglong2* vp = (const ulonglong2*)vs[hh][t];
            #pragma unroll
            for (int i = 0; i < 8; i++) {
                ulonglong2 va = vp[i];
                fma2(a2[2*i],   p2, va.x);
                fma2(a2[2*i+1], p2, va.y);
            }
        }
        #pragma unroll
        for (int j = 0; j < 8; j++) {
            float2 u0 = unpack2(a2[2*j]);
            float2 u1 = unpack2(a2[2*j+1]);
            bf16_store4(oh + qrow + 4*j, make_float4(u0.x, u0.y, u1.x, u1.y));
        }
    }
}

// ---------------- depthwise 3x3 conv + exact GELU, 4-row blocked -------------
__device__ __forceinline__ float gelu_exact(float v)
{
    return 0.5f * v * (1.0f + erff(v * 0.70710678118654752f));
}

__global__ void dwconv_gelu_kernel(const float* __restrict__ h, const float* __restrict__ w,
                                   const float* __restrict__ bias,
                                   __nv_bfloat16* __restrict__ oh)
{
    int t = blockIdx.x * blockDim.x + threadIdx.x;
    int c4 = t & 255;
    int rest = t >> 8;
    int xx = rest % HW;
    int tmp = rest / HW;
    int y4 = tmp % (HW/4);
    int bb = tmp / (HW/4);
    int yy0 = y4 * 4;
    int c  = c4 * 4;

    float wv[4][9];
    #pragma unroll
    for (int e = 0; e < 4; e++) {
        #pragma unroll
        for (int k = 0; k < 9; k++) {
            wv[e][k] = w[(c+e)*9 + k];
        }
    }

    float4 bz = *(const float4*)&bias[c];
    float4 acc[4];
    #pragma unroll
    for (int oy = 0; oy < 4; oy++) {
        acc[oy] = bz;
    }

    #pragma unroll
    for (int ry = 0; ry < 6; ry++) {
        int y2 = yy0 - 1 + ry;
        if ((unsigned)y2 >= HW) continue;
        #pragma unroll
        for (int dx = 0; dx < 3; dx++) {
            int x2 = xx + dx - 1;
            if ((unsigned)x2 >= HW) continue;
            float4 v = *(const float4*)&h[((size_t)bb*NTOK + y2*HW + x2) * HID + c];
            #pragma unroll
            for (int oy = 0; oy < 4; oy++) {
                int dy = ry - oy;
                if (dy < 0 || dy > 2) continue;
                int k = dy*3 + dx;
                acc[oy].x = fmaf(v.x, wv[0][k], acc[oy].x);
                acc[oy].y = fmaf(v.y, wv[1][k], acc[oy].y);
                acc[oy].z = fmaf(v.z, wv[2][k], acc[oy].z);
                acc[oy].w = fmaf(v.w, wv[3][k], acc[oy].w);
            }
        }
    }

    #pragma unroll
    for (int oy = 0; oy < 4; oy++) {
        float4 a = acc[oy];
        a.x = gelu_exact(a.x);
        a.y = gelu_exact(a.y);
        a.z = gelu_exact(a.z);
        a.w = gelu_exact(a.w);
        size_t off = ((size_t)bb*NTOK + (yy0+oy)*HW + xx) * HID + c;
        bf16_store4(oh + off, a);
    }
}

// ---------------- persistent host objects (created once, reused) -------------
static cudaStream_t h_s1 = 0;
static cudaStream_t h_s2 = 0;
static cudaEvent_t  h_e_wt = 0, h_e_ln = 0, h_e_q = 0, h_e_gkv = 0, h_e_lp = 0, h_e_fork = 0;
static int h_objs_ready = 0;

// ---------------- launch (stream-parallel DAG inside graph capture) ----------
extern "C" void kernel_launch(void* const* d_in, const int* in_sizes, int n_in,
                              void* d_out, int out_size)
{
    const float* x     = (const float*)d_in[0];
    const float* xr    = (const float*)d_in[1];
    const float* g1    = (const float*)d_in[2];
    const float* b1    = (const float*)d_in[3];
    const float* g2    = (const float*)d_in[4];
    const float* b2    = (const float*)d_in[5];
    const float* Gq_w  = (const float*)d_in[6];
    const float* Gq_b  = (const float*)d_in[7];
    const float* Gkv_w = (const float*)d_in[8];
    const float* Gkv_b = (const float*)d_in[9];
    const float* Gp_w  = (const float*)d_in[10];
    const float* Gp_b  = (const float*)d_in[11];
    const float* Lq_w  = (const float*)d_in[12];
    const float* Lq_b  = (const float*)d_in[13];
    const float* Lkv_w = (const float*)d_in[14];
    const float* Lkv_b = (const float*)d_in[15];
    const float* Lp_w  = (const float*)d_in[16];
    const float* Lp_b  = (const float*)d_in[17];
    const float* fc1_w = (const float*)d_in[18];
    const float* fc1_b = (const float*)d_in[19];
    const float* dw_w  = (const float*)d_in[20];
    const float* dw_b  = (const float*)d_in[21];
    const float* fc2_w = (const float*)d_in[22];
    const float* fc2_b = (const float*)d_in[23];
    float* out = (float*)d_out;

    __nv_bfloat16 *p_xn;
    __nv_bfloat16 *p_xrn;
    __nv_bfloat16 *p_pool;
    __nv_bfloat16 *p_att;
    __nv_bfloat16 *p_ln2;
    __nv_bfloat16 *p_h2;
    float *p_qq;
    float *p_kv;
    float *p_kvl;
    float *p_cat;
    float *p_h1;
    float *p_bq;
    __nv_bfloat16 *p_wq_h;
    __nv_bfloat16 *p_wq_l;
    __nv_bfloat16 *p_wkv_h;
    __nv_bfloat16 *p_wkv_l;
    __nv_bfloat16 *p_wlkv_h;
    __nv_bfloat16 *p_wlkv_l;
    __nv_bfloat16 *p_wgp_h;
    __nv_bfloat16 *p_wgp_l;
    __nv_bfloat16 *p_wlp_h;
    __nv_bfloat16 *p_wlp_l;
    __nv_bfloat16 *p_wfc1_h;
    __nv_bfloat16 *p_wfc1_l;
    __nv_bfloat16 *p_wfc2_h;
    __nv_bfloat16 *p_wfc2_l;

    cudaGetSymbolAddress((void**)&p_xn, g_xn);
    cudaGetSymbolAddress((void**)&p_xrn, g_xrn);
    cudaGetSymbolAddress((void**)&p_pool, g_pool);
    cudaGetSymbolAddress((void**)&p_att, g_att);
    cudaGetSymbolAddress((void**)&p_ln2, g_ln2);
    cudaGetSymbolAddress((void**)&p_h2, g_h2);
    cudaGetSymbolAddress((void**)&p_qq, g_qq);
    cudaGetSymbolAddress((void**)&p_kv, g_kv);
    cudaGetSymbolAddress((void**)&p_kvl, g_kvl);
    cudaGetSymbolAddress((void**)&p_cat, g_cat);
    cudaGetSymbolAddress((void**)&p_h1, g_h1);
    cudaGetSymbolAddress((void**)&p_bq, b_q);
    cudaGetSymbolAddress((void**)&p_wq_h, w_q_h);
    cudaGetSymbolAddress((void**)&p_wq_l, w_q_l);
    cudaGetSymbolAddress((void**)&p_wkv_h, w_kv_h);
    cudaGetSymbolAddress((void**)&p_wkv_l, w_kv_l);
    cudaGetSymbolAddress((void**)&p_wlkv_h, w_lkv_h);
    cudaGetSymbolAddress((void**)&p_wlkv_l, w_lkv_l);
    cudaGetSymbolAddress((void**)&p_wgp_h, w_gp_h);
    cudaGetSymbolAddress((void**)&p_wgp_l, w_gp_l);
    cudaGetSymbolAddress((void**)&p_wlp_h, w_lp_h);
    cudaGetSymbolAddress((void**)&p_wlp_l, w_lp_l);
    cudaGetSymbolAddress((void**)&p_wfc1_h, w_fc1_h);
    cudaGetSymbolAddress((void**)&p_wfc1_l, w_fc1_l);
    cudaGetSymbolAddress((void**)&p_wfc2_h, w_fc2_h);
    cudaGetSymbolAddress((void**)&p_wfc2_l, w_fc2_l);

    const int SMEM = 2 * STG * (int)sizeof(__nv_bfloat16);   // 61440
    cudaFuncSetAttribute(mma_gemm, cudaFuncAttributeMaxDynamicSharedMemorySize, SMEM);

    if (!h_objs_ready) {
        cudaStreamCreateWithFlags(&h_s1, cudaStreamNonBlocking);
        cudaStreamCreateWithFlags(&h_s2, cudaStreamNonBlocking);
        cudaEventCreateWithFlags(&h_e_wt,   cudaEventDisableTiming);
        cudaEventCreateWithFlags(&h_e_ln,   cudaEventDisableTiming);
        cudaEventCreateWithFlags(&h_e_q,    cudaEventDisableTiming);
        cudaEventCreateWithFlags(&h_e_gkv,  cudaEventDisableTiming);
        cudaEventCreateWithFlags(&h_e_lp,   cudaEventDisableTiming);
        cudaEventCreateWithFlags(&h_e_fork, cudaEventDisableTiming);
        h_objs_ready = 1;
    }
    cudaStream_t s1 = h_s1;
    cudaStream_t s2 = h_s2;

    // fork s1/s2 off the capture stream so they join the capture
    cudaEventRecord(h_e_fork, 0);
    cudaStreamWaitEvent(s1, h_e_fork, 0);
    cudaStreamWaitEvent(s2, h_e_fork, 0);

    // s1: weight transpose (independent of LN)
    wtrans_all<<<2945, 256, 0, s1>>>(Gq_w, Gkv_w, Gp_w, Lq_w, Lkv_w, Lp_w,
                                     fc1_w, fc2_w, Gq_b, Lq_b);
    cudaEventRecord(h_e_wt, s1);

    // s0: both LayerNorms
    ln_kernel<<<ROWS/8, 256>>>(x,  g1, b1, p_xn,  ROWS);
    ln_kernel<<<ROWS/8, 256>>>(xr, g1, b1, p_xrn, ROWS);
    cudaEventRecord(h_e_ln, 0);

    // s0: Q projection (needs ln(x) + weights)
    cudaStreamWaitEvent(0, h_e_wt, 0);
    mma_gemm<<<dim3(2, ROWS/128), 256, SMEM>>>(p_xn, p_wq_h, p_wq_l, p_bq, 0,
                                               p_qq, ROWS, 256, CDIM, CDIM, 256, 0);
    cudaEventRecord(h_e_q, 0);

    // s2: pool -> Gkv (needs ln(xr) + weights)
    cudaStreamWaitEvent(s2, h_e_ln, 0);
    cudaStreamWaitEvent(s2, h_e_wt, 0);
    pool_kernel<<<(BATCH*MPOOL*CDIM)/256, 256, 0, s2>>>(p_xrn, p_pool);
    mma_gemm<<<dim3(2, (BATCH*MPOOL)/128), 256, SMEM, s2>>>(p_pool, p_wkv_h, p_wkv_l, Gkv_b, 0,
                                               p_kv, BATCH*MPOOL, 2*GD, CDIM, CDIM, 2*GD, 0);
    cudaEventRecord(h_e_gkv, s2);

    // s1: Lkv projection (needs ln(xr); weights already on s1)
    cudaStreamWaitEvent(s1, h_e_ln, 0);
    mma_gemm<<<dim3(2, ROWS/128), 256, SMEM, s1>>>(p_xrn, p_wlkv_h, p_wlkv_l, Lkv_b, 0,
                                               p_kvl, ROWS, 2*LD, CDIM, CDIM, 2*LD, 0);

    // s0: global attention (needs Q on s0, Gkv on s2)
    cudaStreamWaitEvent(0, h_e_gkv, 0);
    gattn_kernel<<<BATCH*GH*(NTOK/128), 128>>>(p_qq, p_kv, p_att);
    // s0: Gp projection
    mma_gemm<<<dim3(1, ROWS/128), 256, SMEM>>>(p_att, p_wgp_h, p_wgp_l, Gp_b, 0,
                                               p_cat, ROWS, GD, GD, 256, CDIM, 0);

    // s1: local attention (needs Q via e_q; Lkv on s1) then Lp
    cudaStreamWaitEvent(s1, h_e_q, 0);
    lattn_kernel<<<BATCH*256*2, 128, 0, s1>>>(p_qq, p_kvl, p_att);
    mma_gemm<<<dim3(1, ROWS/128), 256, SMEM, s1>>>(p_att + 128, p_wlp_h, p_wlp_l, Lp_b, 0,
                                               p_cat, ROWS, LD, LD, 256, CDIM, GD);
    cudaEventRecord(h_e_lp, s1);

    // s0: join Lp, then fused residual add + ln2, FC1, dwconv, FC2
    cudaStreamWaitEvent(0, h_e_lp, 0);
    addln_kernel<<<ROWS/8, 256>>>(x, p_cat, g2, b2, out, p_ln2);
    mma_gemm<<<dim3(8, ROWS/128), 256, SMEM>>>(p_ln2, p_wfc1_h, p_wfc1_l, fc1_b, 0,
                                               p_h1, ROWS, HID, CDIM, CDIM, HID, 0);
    dwconv_gelu_kernel<<<(BATCH*(HW/4)*HW*256)/256, 256>>>(p_h1, dw_w, dw_b, p_h2);
    mma_gemm<<<dim3(2, ROWS/128), 256, SMEM>>>(p_h2, p_wfc2_h, p_wfc2_l, fc2_b, out,
                                               out, ROWS, CDIM, HID, HID, CDIM, 0);
}

// round 16
// speedup vs baseline: 1.2141x; 1.0039x over previous
#include <cuda_runtime.h>
#include <cuda_bf16.h>
#include <math.h>

// ---------------- problem constants ----------------
#define BATCH 4
#define HW    112
#define NTOK  12544
#define CDIM  256
#define GH    4
#define HD    32
#define GD    128
#define LD    128
#define HID   1024
#define WSZ   7
#define MPOOL 256
#define ROWS  (BATCH*NTOK)
#define ATT_SCALE 0.17677669529663687f

#define PADK  40
#define TILEB (128*PADK)
#define STG   (3*TILEB)          // stage stride: A-hi, B-hi, B-lo

// ---------------- scratch (device globals; no allocation) ----------------
__device__ __align__(256) __nv_bfloat16 g_xn  [ROWS*CDIM];
__device__ __align__(256) __nv_bfloat16 g_xrn [ROWS*CDIM];
__device__ __align__(256) __nv_bfloat16 g_pool[BATCH*MPOOL*CDIM];
__device__ __align__(256) __nv_bfloat16 g_qq [ROWS*256];          // [Gq | Lq]
__device__ __align__(256) __nv_bfloat16 g_kv [BATCH*MPOOL*2*GD];
__device__ __align__(256) __nv_bfloat16 g_kvl[ROWS*2*LD];
__device__ __align__(256) __nv_bfloat16 g_att[ROWS*256];          // [gattn | lattn]
__device__ __align__(256) float g_cat[ROWS*CDIM];
__device__ __align__(256) __nv_bfloat16 g_ln2[ROWS*CDIM];
__device__ __align__(256) __nv_bfloat16 g_h1 [ROWS*HID];
__device__ __align__(256) __nv_bfloat16 g_h2 [ROWS*HID];
// transposed split weights [N][K] + merged bias
__device__ __align__(256) __nv_bfloat16 w_q_h [256*CDIM];
__device__ __align__(256) __nv_bfloat16 w_q_l [256*CDIM];
__device__ __align__(256) __nv_bfloat16 w_kv_h[256*CDIM];
__device__ __align__(256) __nv_bfloat16 w_kv_l[256*CDIM];
__device__ __align__(256) __nv_bfloat16 w_lkv_h[256*CDIM];
__device__ __align__(256) __nv_bfloat16 w_lkv_l[256*CDIM];
__device__ __align__(256) __nv_bfloat16 w_gp_h [GD*GD];
__device__ __align__(256) __nv_bfloat16 w_gp_l [GD*GD];
__device__ __align__(256) __nv_bfloat16 w_lp_h [LD*LD];
__device__ __align__(256) __nv_bfloat16 w_lp_l [LD*LD];
__device__ __align__(256) __nv_bfloat16 w_fc1_h[HID*CDIM];
__device__ __align__(256) __nv_bfloat16 w_fc1_l[HID*CDIM];
__device__ __align__(256) __nv_bfloat16 w_fc2_h[CDIM*HID];
__device__ __align__(256) __nv_bfloat16 w_fc2_l[CDIM*HID];
__device__ __align__(256) float b_q[256];

// ---------------- helpers ----------------
__device__ __forceinline__ void bf16_store4(__nv_bfloat16* p, float4 v)
{
    __nv_bfloat162 h0 = __nv_bfloat162(__float2bfloat16(v.x), __float2bfloat16(v.y));
    __nv_bfloat162 h1 = __nv_bfloat162(__float2bfloat16(v.z), __float2bfloat16(v.w));
    ((__nv_bfloat162*)p)[0] = h0;
    ((__nv_bfloat162*)p)[1] = h1;
}

__device__ __forceinline__ float4 bf16_load4(const __nv_bfloat16* p)
{
    __nv_bfloat162 a = ((const __nv_bfloat162*)p)[0];
    __nv_bfloat162 b = ((const __nv_bfloat162*)p)[1];
    float2 fa = __bfloat1622float2(a);
    float2 fb = __bfloat1622float2(b);
    return make_float4(fa.x, fa.y, fb.x, fb.y);
}

__device__ __forceinline__ unsigned smem_u32(const void* p)
{
    return (unsigned)__cvta_generic_to_shared(p);
}

__device__ __forceinline__ void ldsm4(unsigned* r, unsigned addr)
{
    asm volatile("ldmatrix.sync.aligned.m8n8.x4.shared.b16 {%0,%1,%2,%3}, [%4];"
        : "=r"(r[0]), "=r"(r[1]), "=r"(r[2]), "=r"(r[3]) : "r"(addr));
}

__device__ __forceinline__ void mma_bf16(float* c, const unsigned* a, const unsigned* b)
{
    asm volatile("mma.sync.aligned.m16n8k16.row.col.f32.bf16.bf16.f32 "
        "{%0,%1,%2,%3},{%4,%5,%6,%7},{%8,%9},{%0,%1,%2,%3};"
        : "+f"(c[0]), "+f"(c[1]), "+f"(c[2]), "+f"(c[3])
        : "r"(a[0]), "r"(a[1]), "r"(a[2]), "r"(a[3]), "r"(b[0]), "r"(b[1]));
}

__device__ __forceinline__ void cpa16(unsigned saddr, const void* g)
{
    asm volatile("cp.async.cg.shared.global [%0], [%1], 16;" :: "r"(saddr), "l"(g) : "memory");
}

// ---- packed f32x2 math ----
__device__ __forceinline__ void fma2(unsigned long long& d, unsigned long long a,
                                     unsigned long long b)
{
    asm("fma.rn.f32x2 %0, %1, %2, %0;" : "+l"(d) : "l"(a), "l"(b));
}

__device__ __forceinline__ void mul2(unsigned long long& d, unsigned long long c)
{
    asm("mul.rn.f32x2 %0, %0, %1;" : "+l"(d) : "l"(c));
}

__device__ __forceinline__ unsigned long long pack2(float x)
{
    unsigned long long r;
    asm("mov.b64 %0, {%1, %1};" : "=l"(r) : "f"(x));
    return r;
}

__device__ __forceinline__ unsigned long long packf2(float2 f)
{
    unsigned long long r;
    asm("mov.b64 %0, {%1, %2};" : "=l"(r) : "f"(f.x), "f"(f.y));
    return r;
}

__device__ __forceinline__ float2 unpack2(unsigned long long v)
{
    float2 f;
    asm("mov.b64 {%0, %1}, %2;" : "=f"(f.x), "=f"(f.y) : "l"(v));
    return f;
}

// stage loader: 256 threads, 3 tiles (A-hi, B-hi, B-lo) x 512 16B-chunks
__device__ __forceinline__ void gemm_stage(
    __nv_bfloat16* sbase, int tid,
    const __nv_bfloat16* Ah,
    const __nv_bfloat16* Bh, const __nv_bfloat16* Bl,
    int bm, int bn, int K, int lda, int k0)
{
    __nv_bfloat16* sA  = sbase;
    __nv_bfloat16* sB0 = sbase + TILEB;
    __nv_bfloat16* sB1 = sbase + 2*TILEB;
    #pragma unroll
    for (int j = 0; j < 2; j++) {
        int u = tid + 256*j;
        int row = u >> 2;
        int qq = u & 3;
        int so = row * PADK + qq * 8;
        size_t gA = (size_t)(bm + row) * lda + k0 + qq * 8;
        size_t gB = (size_t)(bn + row) * K + k0 + qq * 8;
        cpa16(smem_u32(sA  + so), Ah + gA);
        cpa16(smem_u32(sB0 + so), Bh + gB);
        cpa16(smem_u32(sB1 + so), Bl + gB);
    }
}

// ---------------- single-launch weight transpose + split ----------------
__device__ __forceinline__ void wt_store(__nv_bfloat16* hi, __nv_bfloat16* lo,
                                         int t, float v)
{
    __nv_bfloat16 h = __float2bfloat16(v);
    hi[t] = h;
    lo[t] = __float2bfloat16(v - __bfloat162float(h));
}

__global__ void wtrans_all(const float* __restrict__ Gq, const float* __restrict__ Gkv,
                           const float* __restrict__ Gp, const float* __restrict__ Lq,
                           const float* __restrict__ Lkv, const float* __restrict__ Lp,
                           const float* __restrict__ fc1, const float* __restrict__ fc2,
                           const float* __restrict__ Gq_b, const float* __restrict__ Lq_b)
{
    int t = blockIdx.x * blockDim.x + threadIdx.x;
    if (t < 65536) {
        int n = t >> 8;
        int k = t & 255;
        float v = (n < 128) ? Gq[(size_t)k*128 + n] : Lq[(size_t)k*128 + (n-128)];
        wt_store(w_q_h, w_q_l, t, v);
    } else if (t < 131072) {
        int u = t - 65536;
        int n = u >> 8;
        int k = u & 255;
        wt_store(w_kv_h, w_kv_l, u, Gkv[(size_t)k*256 + n]);
    } else if (t < 196608) {
        int u = t - 131072;
        int n = u >> 8;
        int k = u & 255;
        wt_store(w_lkv_h, w_lkv_l, u, Lkv[(size_t)k*256 + n]);
    } else if (t < 212992) {
        int u = t - 196608;
        int n = u >> 7;
        int k = u & 127;
        wt_store(w_gp_h, w_gp_l, u, Gp[(size_t)k*128 + n]);
    } else if (t < 229376) {
        int u = t - 212992;
        int n = u >> 7;
        int k = u & 127;
        wt_store(w_lp_h, w_lp_l, u, Lp[(size_t)k*128 + n]);
    } else if (t < 491520) {
        int u = t - 229376;
        int n = u >> 8;
        int k = u & 255;
        wt_store(w_fc1_h, w_fc1_l, u, fc1[(size_t)k*1024 + n]);
    } else if (t < 753664) {
        int u = t - 491520;
        int n = u / 1024;
        int k = u - n * 1024;
        wt_store(w_fc2_h, w_fc2_l, u, fc2[(size_t)k*256 + n]);
    } else if (t < 753920) {
        int u = t - 753664;
        b_q[u] = (u < 128) ? Gq_b[u] : Lq_b[u-128];
    }
}

// ---------------- LayerNorm (ln1, bf16 out) ----------------
__global__ void ln_kernel(const float* __restrict__ x, const float* __restrict__ g,
                          const float* __restrict__ b,
                          __nv_bfloat16* __restrict__ oh, int rows)
{
    int gw   = (blockIdx.x * blockDim.x + threadIdx.x) >> 5;
    int lane = threadIdx.x & 31;
    if (gw >= rows) return;
    const float4* xr = (const float4*)(x + (size_t)gw * CDIM);
    float4 v0 = xr[lane];
    float4 v1 = xr[lane + 32];
    float s  = v0.x+v0.y+v0.z+v0.w + v1.x+v1.y+v1.z+v1.w;
    float ss = v0.x*v0.x+v0.y*v0.y+v0.z*v0.z+v0.w*v0.w
             + v1.x*v1.x+v1.y*v1.y+v1.z*v1.z+v1.w*v1.w;
    #pragma unroll
    for (int o = 16; o; o >>= 1) {
        s  += __shfl_xor_sync(0xffffffffu, s,  o);
        ss += __shfl_xor_sync(0xffffffffu, ss, o);
    }
    float mean = s * (1.0f/CDIM);
    float var  = ss * (1.0f/CDIM) - mean*mean;
    float inv  = rsqrtf(var + 1e-5f);
    const float4* g4 = (const float4*)g;
    const float4* b4 = (const float4*)b;
    float4 G0 = g4[lane];
    float4 B0 = b4[lane];
    float4 G1 = g4[lane+32];
    float4 B1 = b4[lane+32];
    float4 o0, o1;
    o0.x = (v0.x-mean)*inv*G0.x + B0.x;
    o0.y = (v0.y-mean)*inv*G0.y + B0.y;
    o0.z = (v0.z-mean)*inv*G0.z + B0.z;
    o0.w = (v0.w-mean)*inv*G0.w + B0.w;
    o1.x = (v1.x-mean)*inv*G1.x + B1.x;
    o1.y = (v1.y-mean)*inv*G1.y + B1.y;
    o1.z = (v1.z-mean)*inv*G1.z + B1.z;
    o1.w = (v1.w-mean)*inv*G1.w + B1.w;
    size_t base = (size_t)gw * CDIM + lane * 4;
    bf16_store4(oh + base,       o0);
    bf16_store4(oh + base + 128, o1);
}

// ---------------- fused residual add + LayerNorm (ln2, bf16 out) -------------
__global__ void addln_kernel(const float* __restrict__ x, const float* __restrict__ cat,
                             const float* __restrict__ g, const float* __restrict__ b,
                             float* __restrict__ out, __nv_bfloat16* __restrict__ oh)
{
    int gw   = (blockIdx.x * blockDim.x + threadIdx.x) >> 5;
    int lane = threadIdx.x & 31;
    const float4* xr = (const float4*)(x + (size_t)gw * CDIM);
    const float4* cr = (const float4*)(cat + (size_t)gw * CDIM);
    float4 a0 = xr[lane];
    float4 a1 = xr[lane + 32];
    float4 c0 = cr[lane];
    float4 c1 = cr[lane + 32];
    float4 v0 = make_float4(a0.x+c0.x, a0.y+c0.y, a0.z+c0.z, a0.w+c0.w);
    float4 v1 = make_float4(a1.x+c1.x, a1.y+c1.y, a1.z+c1.z, a1.w+c1.w);
    float4* orow = (float4*)(out + (size_t)gw * CDIM);
    orow[lane]      = v0;
    orow[lane + 32] = v1;
    float s  = v0.x+v0.y+v0.z+v0.w + v1.x+v1.y+v1.z+v1.w;
    float ss = v0.x*v0.x+v0.y*v0.y+v0.z*v0.z+v0.w*v0.w
             + v1.x*v1.x+v1.y*v1.y+v1.z*v1.z+v1.w*v1.w;
    #pragma unroll
    for (int o = 16; o; o >>= 1) {
        s  += __shfl_xor_sync(0xffffffffu, s,  o);
        ss += __shfl_xor_sync(0xffffffffu, ss, o);
    }
    float mean = s * (1.0f/CDIM);
    float var  = ss * (1.0f/CDIM) - mean*mean;
    float inv  = rsqrtf(var + 1e-5f);
    const float4* g4 = (const float4*)g;
    const float4* b4 = (const float4*)b;
    float4 G0 = g4[lane];
    float4 B0 = b4[lane];
    float4 G1 = g4[lane+32];
    float4 B1 = b4[lane+32];
    float4 o0, o1;
    o0.x = (v0.x-mean)*inv*G0.x + B0.x;
    o0.y = (v0.y-mean)*inv*G0.y + B0.y;
    o0.z = (v0.z-mean)*inv*G0.z + B0.z;
    o0.w = (v0.w-mean)*inv*G0.w + B0.w;
    o1.x = (v1.x-mean)*inv*G1.x + B1.x;
    o1.y = (v1.y-mean)*inv*G1.y + B1.y;
    o1.z = (v1.z-mean)*inv*G1.z + B1.z;
    o1.w = (v1.w-mean)*inv*G1.w + B1.w;
    size_t base = (size_t)gw * CDIM + lane * 4;
    bf16_store4(oh + base,       o0);
    bf16_store4(oh + base + 128, o1);
}

// ---------------- 7x7 mean pooling (bf16 in/out) ----------------
__global__ void pool_kernel(const __nv_bfloat16* __restrict__ xh,
                            __nv_bfloat16* __restrict__ ph)
{
    int t = blockIdx.x * blockDim.x + threadIdx.x;
    int c = t & 255;
    int g = (t >> 8) & 255;
    int b = t >> 16;
    int gy = g >> 4;
    int gx = g & 15;
    float s = 0.0f;
    #pragma unroll
    for (int py = 0; py < WSZ; py++) {
        int rowbase = (gy*WSZ + py) * HW + gx*WSZ;
        #pragma unroll
        for (int px = 0; px < WSZ; px++) {
            size_t idx = ((size_t)b*NTOK + rowbase + px) * CDIM + c;
            s += __bfloat162float(xh[idx]);
        }
    }
    ph[t] = __float2bfloat16(s * (1.0f/49.0f));
}

// ---------------- tensor-core bf16x2 GEMM: A-hi x (B-hi + B-lo) --------------
// obf=0: C(float*) = (addsrc?) + A@B^T + bias ; obf=1: C(bf16*), no addsrc
__global__ void __launch_bounds__(256, 2) mma_gemm(
    const __nv_bfloat16* __restrict__ Ah,
    const __nv_bfloat16* __restrict__ Bh, const __nv_bfloat16* __restrict__ Bl,
    const float* __restrict__ bias, const float* __restrict__ addsrc,
    void* __restrict__ Cv, int M, int N, int K, int lda, int ldc, int coff, int obf)
{
    extern __shared__ __nv_bfloat16 sh[];
    int tid  = threadIdx.x;
    int lane = tid & 31;
    int warp = tid >> 5;
    int wm = (warp & 3) * 32;
    int wn = (warp >> 2) * 64;
    int bm = blockIdx.y * 128;
    int bn = blockIdx.x * 128;

    float acc[2][8][4];
    #pragma unroll
    for (int i = 0; i < 2; i++) {
        #pragma unroll
        for (int j = 0; j < 8; j++) {
            #pragma unroll
            for (int e = 0; e < 4; e++) {
                acc[i][j][e] = 0.0f;
            }
        }
    }

    int nIter = K >> 5;

    gemm_stage(sh, tid, Ah, Bh, Bl, bm, bn, K, lda, 0);
    asm volatile("cp.async.commit_group;" ::: "memory");

    for (int it = 0; it < nIter; it++) {
        int st = it & 1;
        if (it + 1 < nIter) {
            gemm_stage(sh + (st^1)*STG, tid, Ah, Bh, Bl, bm, bn, K, lda, (it+1) << 5);
            asm volatile("cp.async.commit_group;" ::: "memory");
            asm volatile("cp.async.wait_group 1;" ::: "memory");
        } else {
            asm volatile("cp.async.wait_group 0;" ::: "memory");
        }
        __syncthreads();

        const __nv_bfloat16* cA  = sh + st*STG;
        const __nv_bfloat16* cB0 = cA + TILEB;
        const __nv_bfloat16* cB1 = cA + 2*TILEB;

        #pragma unroll
        for (int kk = 0; kk < 2; kk++) {
            unsigned afh[2][4];
            #pragma unroll
            for (int mi = 0; mi < 2; mi++) {
                int row = wm + mi*16 + (lane & 15);
                int col = kk*16 + (lane >> 4) * 8;
                ldsm4(afh[mi], smem_u32(cA + row*PADK + col));
            }
            #pragma unroll
            for (int np = 0; np < 4; np++) {
                unsigned bfh[4];
                unsigned bfl[4];
                int row = wn + np*16 + (lane >> 4) * 8 + (lane & 7);
                int col = kk*16 + ((lane >> 3) & 1) * 8;
                ldsm4(bfh, smem_u32(cB0 + row*PADK + col));
                ldsm4(bfl, smem_u32(cB1 + row*PADK + col));
                #pragma unroll
                for (int mi = 0; mi < 2; mi++) {
                    mma_bf16(acc[mi][2*np],   afh[mi], &bfh[0]);
                    mma_bf16(acc[mi][2*np+1], afh[mi], &bfh[2]);
                    mma_bf16(acc[mi][2*np],   afh[mi], &bfl[0]);
                    mma_bf16(acc[mi][2*np+1], afh[mi], &bfl[2]);
                }
            }
        }
        __syncthreads();
    }

    int gg = lane >> 2;
    int t2 = (lane & 3) * 2;
    #pragma unroll
    for (int mi = 0; mi < 2; mi++) {
        #pragma unroll
        for (int half = 0; half < 2; half++) {
            int row = bm + wm + mi*16 + gg + half*8;
            #pragma unroll
            for (int ni = 0; ni < 8; ni++) {
                int col = bn + wn + ni*8 + t2;
                float2 bv = *(const float2*)&bias[col];
                float v0 = acc[mi][ni][half*2 + 0] + bv.x;
                float v1 = acc[mi][ni][half*2 + 1] + bv.y;
                size_t off = (size_t)row * ldc + coff + col;
                if (obf) {
                    __nv_bfloat16* Cb = (__nv_bfloat16*)Cv;
                    ((__nv_bfloat162*)&Cb[off])[0] =
                        __nv_bfloat162(__float2bfloat16(v0), __float2bfloat16(v1));
                } else {
                    float* C = (float*)Cv;
                    if (addsrc) {
                        float2 sv = *(const float2*)&addsrc[off];
                        v0 += sv.x;
                        v1 += sv.y;
                    }
                    *(float2*)&C[off] = make_float2(v0, v1);
                }
            }
        }
    }
}

// ---------------- global attention (bf16 q/kv in, bf16 out) ----------------
__global__ void __launch_bounds__(128) gattn_kernel(
    const __nv_bfloat16* __restrict__ q, const __nv_bfloat16* __restrict__ kv,
    __nv_bfloat16* __restrict__ oh)
{
    __shared__ float ks[128][HD];
    __shared__ float vs[128][HD];
    int bi = blockIdx.x;
    int qc = bi % (NTOK/128);
    int h  = (bi / (NTOK/128)) & (GH-1);
    int b  = bi / ((NTOK/128) * GH);
    int tid = threadIdx.x;
    int n   = qc*128 + tid;
    size_t qrow = (size_t)(b*NTOK + n) * 256 + h*HD;

    unsigned long long q2[16];
    {
        const __nv_bfloat162* qp = (const __nv_bfloat162*)&q[qrow];
        #pragma unroll
        for (int j = 0; j < 16; j++) {
            q2[j] = packf2(__bfloat1622float2(qp[j]));
        }
    }

    float mx = -INFINITY;
    float l = 0.0f;
    unsigned long long a2[16];
    #pragma unroll
    for (int d = 0; d < 16; d++) {
        a2[d] = 0ULL;
    }

    for (int ch = 0; ch < 2; ch++) {
        #pragma unroll
        for (int j = 0; j < 8; j++) {
            int f4 = tid + 128*j;
            int m  = f4 >> 3;
            int d4 = (f4 & 7) * 4;
            size_t kvrow = (size_t)(b*MPOOL + ch*128 + m) * (2*GD) + h*HD;
            *(float4*)&ks[m][d4] = bf16_load4(&kv[kvrow + d4]);
            *(float4*)&vs[m][d4] = bf16_load4(&kv[kvrow + GD + d4]);
        }
        __syncthreads();
        for (int m = 0; m < 128; m++) {
            const ulonglong2* kp = (const ulonglong2*)ks[m];
            unsigned long long s0 = 0ULL, s1 = 0ULL, s2 = 0ULL, s3 = 0ULL;
            #pragma unroll
            for (int i = 0; i < 4; i++) {
                ulonglong2 ka = kp[2*i];
                ulonglong2 kb = kp[2*i+1];
                fma2(s0, q2[4*i+0], ka.x);
                fma2(s1, q2[4*i+1], ka.y);
                fma2(s2, q2[4*i+2], kb.x);
                fma2(s3, q2[4*i+3], kb.y);
            }
            float2 f0 = unpack2(s0);
            float2 f1 = unpack2(s1);
            float2 f2 = unpack2(s2);
            float2 f3 = unpack2(s3);
            float sdot = (f0.x + f0.y) + (f1.x + f1.y) + (f2.x + f2.y) + (f3.x + f3.y);
            float sc = sdot * ATT_SCALE;
            if (sc > mx) {
                float corr = __expf(mx - sc);
                l *= corr;
                unsigned long long c2 = pack2(corr);
                #pragma unroll
                for (int d = 0; d < 16; d++) {
                    mul2(a2[d], c2);
                }
                mx = sc;
            }
            float p = __expf(sc - mx);
            l += p;
            unsigned long long p2 = pack2(p);
            const ulonglong2* vp = (const ulonglong2*)vs[m];
            #pragma unroll
            for (int i = 0; i < 8; i++) {
                ulonglong2 va = vp[i];
                fma2(a2[2*i],   p2, va.x);
                fma2(a2[2*i+1], p2, va.y);
            }
        }
        __syncthreads();
    }

    float inv = 1.0f / l;
    #pragma unroll
    for (int j = 0; j < 8; j++) {
        float2 u0 = unpack2(a2[2*j]);
        float2 u1 = unpack2(a2[2*j+1]);
        bf16_store4(oh + qrow + 4*j, make_float4(u0.x*inv, u0.y*inv, u1.x*inv, u1.y*inv));
    }
}

// ---------------- local window attention (bf16 q/kv in, bf16 out) ------------
__global__ void __launch_bounds__(128) lattn_kernel(
    const __nv_bfloat16* __restrict__ ql, const __nv_bfloat16* __restrict__ kvl,
    __nv_bfloat16* __restrict__ oh)
{
    __shared__ float ks[2][49][HD];
    __shared__ float vs[2][49][HD];
    int bi = blockIdx.x;
    int hp = bi & 1;
    int wi = (bi >> 1) & 255;
    int b  = bi >> 9;
    int wy = wi >> 4;
    int wx = wi & 15;
    int tid = threadIdx.x;

    for (int i = tid; i < 2*49*8; i += 128) {
        int d4 = (i & 7) * 4;
        int t  = (i >> 3) % 49;
        int hh = i / (49*8);
        int py = t / WSZ;
        int px = t % WSZ;
        int n  = (wy*WSZ + py)*HW + wx*WSZ + px;
        size_t rowb = (size_t)(b*NTOK + n) * (2*LD) + (hp*2 + hh)*HD;
        *(float4*)&ks[hh][t][d4] = bf16_load4(&kvl[rowb + d4]);
        *(float4*)&vs[hh][t][d4] = bf16_load4(&kvl[rowb + LD + d4]);
    }
    __syncthreads();

    if (tid < 98) {
        int hh = tid / 49;
        int qi = tid % 49;
        int h  = hp*2 + hh;
        int py = qi / WSZ;
        int px = qi % WSZ;
        int n  = (wy*WSZ + py)*HW + wx*WSZ + px;
        size_t qrow = (size_t)(b*NTOK + n) * 256 + 128 + h*HD;

        unsigned long long q2[16];
        {
            const __nv_bfloat162* qp = (const __nv_bfloat162*)&ql[qrow];
            #pragma unroll
            for (int j = 0; j < 16; j++) {
                q2[j] = packf2(__bfloat1622float2(qp[j]));
            }
        }

        float sc[49];
        float mx = -INFINITY;
        #pragma unroll
        for (int t = 0; t < 49; t++) {
            const ulonglong2* kp = (const ulonglong2*)ks[hh][t];
            unsigned long long s0 = 0ULL, s1 = 0ULL, s2 = 0ULL, s3 = 0ULL;
            #pragma unroll
            for (int i = 0; i < 4; i++) {
                ulonglong2 ka = kp[2*i];
                ulonglong2 kb = kp[2*i+1];
                fma2(s0, q2[4*i+0], ka.x);
                fma2(s1, q2[4*i+1], ka.y);
                fma2(s2, q2[4*i+2], kb.x);
                fma2(s3, q2[4*i+3], kb.y);
            }
            float2 f0 = unpack2(s0);
            float2 f1 = unpack2(s1);
            float2 f2 = unpack2(s2);
            float2 f3 = unpack2(s3);
            float s = ((f0.x + f0.y) + (f1.x + f1.y) + (f2.x + f2.y) + (f3.x + f3.y)) * ATT_SCALE;
            sc[t] = s;
            mx = fmaxf(mx, s);
        }
        float l = 0.0f;
        #pragma unroll
        for (int t = 0; t < 49; t++) {
            sc[t] = __expf(sc[t] - mx);
            l += sc[t];
        }
        float inv = 1.0f / l;

        unsigned long long a2[16];
        #pragma unroll
        for (int d = 0; d < 16; d++) {
            a2[d] = 0ULL;
        }
        #pragma unroll
        for (int t = 0; t < 49; t++) {
            unsigned long long p2 = pack2(sc[t] * inv);
            const ulonglong2* vp = (const ulonglong2*)vs[hh][t];
            #pragma unroll
            for (int i = 0; i < 8; i++) {
                ulonglong2 va = vp[i];
                fma2(a2[2*i],   p2, va.x);
                fma2(a2[2*i+1], p2, va.y);
            }
        }
        #pragma unroll
        for (int j = 0; j < 8; j++) {
            float2 u0 = unpack2(a2[2*j]);
            float2 u1 = unpack2(a2[2*j+1]);
            bf16_store4(oh + qrow + 4*j, make_float4(u0.x, u0.y, u1.x, u1.y));
        }
    }
}

// ---------------- depthwise 3x3 conv + exact GELU, 4-row blocked -------------
__device__ __forceinline__ float gelu_exact(float v)
{
    return 0.5f * v * (1.0f + erff(v * 0.70710678118654752f));
}

__global__ void dwconv_gelu_kernel(const __nv_bfloat16* __restrict__ h,
                                   const float* __restrict__ w,
                                   const float* __restrict__ bias,
                                   __nv_bfloat16* __restrict__ oh)
{
    int t = blockIdx.x * blockDim.x + threadIdx.x;
    int c4 = t & 255;
    int rest = t >> 8;
    int xx = rest % HW;
    int tmp = rest / HW;
    int y4 = tmp % (HW/4);
    int bb = tmp / (HW/4);
    int yy0 = y4 * 4;
    int c  = c4 * 4;

    float wv[4][9];
    #pragma unroll
    for (int e = 0; e < 4; e++) {
        #pragma unroll
        for (int k = 0; k < 9; k++) {
            wv[e][k] = w[(c+e)*9 + k];
        }
    }

    float4 bz = *(const float4*)&bias[c];
    float4 acc[4];
    #pragma unroll
    for (int oy = 0; oy < 4; oy++) {
        acc[oy] = bz;
    }

    #pragma unroll
    for (int ry = 0; ry < 6; ry++) {
        int y2 = yy0 - 1 + ry;
        if ((unsigned)y2 >= HW) continue;
        #pragma unroll
        for (int dx = 0; dx < 3; dx++) {
            int x2 = xx + dx - 1;
            if ((unsigned)x2 >= HW) continue;
            float4 v = bf16_load4(&h[((size_t)bb*NTOK + y2*HW + x2) * HID + c]);
            #pragma unroll
            for (int oy = 0; oy < 4; oy++) {
                int dy = ry - oy;
                if (dy < 0 || dy > 2) continue;
                int k = dy*3 + dx;
                acc[oy].x = fmaf(v.x, wv[0][k], acc[oy].x);
                acc[oy].y = fmaf(v.y, wv[1][k], acc[oy].y);
                acc[oy].z = fmaf(v.z, wv[2][k], acc[oy].z);
                acc[oy].w = fmaf(v.w, wv[3][k], acc[oy].w);
            }
        }
    }

    #pragma unroll
    for (int oy = 0; oy < 4; oy++) {
        float4 a = acc[oy];
        a.x = gelu_exact(a.x);
        a.y = gelu_exact(a.y);
        a.z = gelu_exact(a.z);
        a.w = gelu_exact(a.w);
        size_t off = ((size_t)bb*NTOK + (yy0+oy)*HW + xx) * HID + c;
        bf16_store4(oh + off, a);
    }
}

// ---------------- persistent host objects (created once, reused) -------------
static cudaStream_t h_s1 = 0;
static cudaStream_t h_s2 = 0;
static cudaEvent_t  h_e_wt = 0, h_e_ln = 0, h_e_q = 0, h_e_gkv = 0, h_e_lp = 0, h_e_fork = 0;
static int h_objs_ready = 0;

// ---------------- launch (stream-parallel DAG inside graph capture) ----------
extern "C" void kernel_launch(void* const* d_in, const int* in_sizes, int n_in,
                              void* d_out, int out_size)
{
    const float* x     = (const float*)d_in[0];
    const float* xr    = (const float*)d_in[1];
    const float* g1    = (const float*)d_in[2];
    const float* b1    = (const float*)d_in[3];
    const float* g2    = (const float*)d_in[4];
    const float* b2    = (const float*)d_in[5];
    const float* Gq_w  = (const float*)d_in[6];
    const float* Gq_b  = (const float*)d_in[7];
    const float* Gkv_w = (const float*)d_in[8];
    const float* Gkv_b = (const float*)d_in[9];
    const float* Gp_w  = (const float*)d_in[10];
    const float* Gp_b  = (const float*)d_in[11];
    const float* Lq_w  = (const float*)d_in[12];
    const float* Lq_b  = (const float*)d_in[13];
    const float* Lkv_w = (const float*)d_in[14];
    const float* Lkv_b = (const float*)d_in[15];
    const float* Lp_w  = (const float*)d_in[16];
    const float* Lp_b  = (const float*)d_in[17];
    const float* fc1_w = (const float*)d_in[18];
    const float* fc1_b = (const float*)d_in[19];
    const float* dw_w  = (const float*)d_in[20];
    const float* dw_b  = (const float*)d_in[21];
    const float* fc2_w = (const float*)d_in[22];
    const float* fc2_b = (const float*)d_in[23];
    float* out = (float*)d_out;

    __nv_bfloat16 *p_xn;
    __nv_bfloat16 *p_xrn;
    __nv_bfloat16 *p_pool;
    __nv_bfloat16 *p_att;
    __nv_bfloat16 *p_ln2;
    __nv_bfloat16 *p_h1;
    __nv_bfloat16 *p_h2;
    __nv_bfloat16 *p_qq;
    __nv_bfloat16 *p_kv;
    __nv_bfloat16 *p_kvl;
    float *p_cat;
    float *p_bq;
    __nv_bfloat16 *p_wq_h;
    __nv_bfloat16 *p_wq_l;
    __nv_bfloat16 *p_wkv_h;
    __nv_bfloat16 *p_wkv_l;
    __nv_bfloat16 *p_wlkv_h;
    __nv_bfloat16 *p_wlkv_l;
    __nv_bfloat16 *p_wgp_h;
    __nv_bfloat16 *p_wgp_l;
    __nv_bfloat16 *p_wlp_h;
    __nv_bfloat16 *p_wlp_l;
    __nv_bfloat16 *p_wfc1_h;
    __nv_bfloat16 *p_wfc1_l;
    __nv_bfloat16 *p_wfc2_h;
    __nv_bfloat16 *p_wfc2_l;

    cudaGetSymbolAddress((void**)&p_xn, g_xn);
    cudaGetSymbolAddress((void**)&p_xrn, g_xrn);
    cudaGetSymbolAddress((void**)&p_pool, g_pool);
    cudaGetSymbolAddress((void**)&p_att, g_att);
    cudaGetSymbolAddress((void**)&p_ln2, g_ln2);
    cudaGetSymbolAddress((void**)&p_h1, g_h1);
    cudaGetSymbolAddress((void**)&p_h2, g_h2);
    cudaGetSymbolAddress((void**)&p_qq, g_qq);
    cudaGetSymbolAddress((void**)&p_kv, g_kv);
    cudaGetSymbolAddress((void**)&p_kvl, g_kvl);
    cudaGetSymbolAddress((void**)&p_cat, g_cat);
    cudaGetSymbolAddress((void**)&p_bq, b_q);
    cudaGetSymbolAddress((void**)&p_wq_h, w_q_h);
    cudaGetSymbolAddress((void**)&p_wq_l, w_q_l);
    cudaGetSymbolAddress((void**)&p_wkv_h, w_kv_h);
    cudaGetSymbolAddress((void**)&p_wkv_l, w_kv_l);
    cudaGetSymbolAddress((void**)&p_wlkv_h, w_lkv_h);
    cudaGetSymbolAddress((void**)&p_wlkv_l, w_lkv_l);
    cudaGetSymbolAddress((void**)&p_wgp_h, w_gp_h);
    cudaGetSymbolAddress((void**)&p_wgp_l, w_gp_l);
    cudaGetSymbolAddress((void**)&p_wlp_h, w_lp_h);
    cudaGetSymbolAddress((void**)&p_wlp_l, w_lp_l);
    cudaGetSymbolAddress((void**)&p_wfc1_h, w_fc1_h);
    cudaGetSymbolAddress((void**)&p_wfc1_l, w_fc1_l);
    cudaGetSymbolAddress((void**)&p_wfc2_h, w_fc2_h);
    cudaGetSymbolAddress((void**)&p_wfc2_l, w_fc2_l);

    const int SMEM = 2 * STG * (int)sizeof(__nv_bfloat16);   // 61440
    cudaFuncSetAttribute(mma_gemm, cudaFuncAttributeMaxDynamicSharedMemorySize, SMEM);

    if (!h_objs_ready) {
        cudaStreamCreateWithFlags(&h_s1, cudaStreamNonBlocking);
        cudaStreamCreateWithFlags(&h_s2, cudaStreamNonBlocking);
        cudaEventCreateWithFlags(&h_e_wt,   cudaEventDisableTiming);
        cudaEventCreateWithFlags(&h_e_ln,   cudaEventDisableTiming);
        cudaEventCreateWithFlags(&h_e_q,    cudaEventDisableTiming);
        cudaEventCreateWithFlags(&h_e_gkv,  cudaEventDisableTiming);
        cudaEventCreateWithFlags(&h_e_lp,   cudaEventDisableTiming);
        cudaEventCreateWithFlags(&h_e_fork, cudaEventDisableTiming);
        h_objs_ready = 1;
    }
    cudaStream_t s1 = h_s1;
    cudaStream_t s2 = h_s2;

    // fork s1/s2 off the capture stream so they join the capture
    cudaEventRecord(h_e_fork, 0);
    cudaStreamWaitEvent(s1, h_e_fork, 0);
    cudaStreamWaitEvent(s2, h_e_fork, 0);

    // s1: weight transpose (independent of LN)
    wtrans_all<<<2945, 256, 0, s1>>>(Gq_w, Gkv_w, Gp_w, Lq_w, Lkv_w, Lp_w,
                                     fc1_w, fc2_w, Gq_b, Lq_b);
    cudaEventRecord(h_e_wt, s1);

    // s0: both LayerNorms
    ln_kernel<<<ROWS/8, 256>>>(x,  g1, b1, p_xn,  ROWS);
    ln_kernel<<<ROWS/8, 256>>>(xr, g1, b1, p_xrn, ROWS);
    cudaEventRecord(h_e_ln, 0);

    // s0: Q projection (bf16 out)
    cudaStreamWaitEvent(0, h_e_wt, 0);
    mma_gemm<<<dim3(2, ROWS/128), 256, SMEM>>>(p_xn, p_wq_h, p_wq_l, p_bq, 0,
                                               p_qq, ROWS, 256, CDIM, CDIM, 256, 0, 1);
    cudaEventRecord(h_e_q, 0);

    // s2: pool -> Gkv (bf16 out)
    cudaStreamWaitEvent(s2, h_e_ln, 0);
    cudaStreamWaitEvent(s2, h_e_wt, 0);
    pool_kernel<<<(BATCH*MPOOL*CDIM)/256, 256, 0, s2>>>(p_xrn, p_pool);
    mma_gemm<<<dim3(2, (BATCH*MPOOL)/128), 256, SMEM, s2>>>(p_pool, p_wkv_h, p_wkv_l, Gkv_b, 0,
                                               p_kv, BATCH*MPOOL, 2*GD, CDIM, CDIM, 2*GD, 0, 1);
    cudaEventRecord(h_e_gkv, s2);

    // s1: Lkv projection (bf16 out)
    cudaStreamWaitEvent(s1, h_e_ln, 0);
    mma_gemm<<<dim3(2, ROWS/128), 256, SMEM, s1>>>(p_xrn, p_wlkv_h, p_wlkv_l, Lkv_b, 0,
                                               p_kvl, ROWS, 2*LD, CDIM, CDIM, 2*LD, 0, 1);

    // s0: global attention (needs Q on s0, Gkv on s2)
    cudaStreamWaitEvent(0, h_e_gkv, 0);
    gattn_kernel<<<BATCH*GH*(NTOK/128), 128>>>(p_qq, p_kv, p_att);
    // s0: Gp projection (fp32 out into cat)
    mma_gemm<<<dim3(1, ROWS/128), 256, SMEM>>>(p_att, p_wgp_h, p_wgp_l, Gp_b, 0,
                                               p_cat, ROWS, GD, GD, 256, CDIM, 0, 0);

    // s1: local attention (needs Q via e_q; Lkv on s1) then Lp
    cudaStreamWaitEvent(s1, h_e_q, 0);
    lattn_kernel<<<BATCH*256*2, 128, 0, s1>>>(p_qq, p_kvl, p_att);
    mma_gemm<<<dim3(1, ROWS/128), 256, SMEM, s1>>>(p_att + 128, p_wlp_h, p_wlp_l, Lp_b, 0,
                                               p_cat, ROWS, LD, LD, 256, CDIM, GD, 0);
    cudaEventRecord(h_e_lp, s1);

    // s0: join Lp, then fused residual add + ln2, FC1 (bf16 out), dwconv, FC2
    cudaStreamWaitEvent(0, h_e_lp, 0);
    addln_kernel<<<ROWS/8, 256>>>(x, p_cat, g2, b2, out, p_ln2);
    mma_gemm<<<dim3(8, ROWS/128), 256, SMEM>>>(p_ln2, p_wfc1_h, p_wfc1_l, fc1_b, 0,
                                               p_h1, ROWS, HID, CDIM, CDIM, HID, 0, 1);
    dwconv_gelu_kernel<<<(BATCH*(HW/4)*HW*256)/256, 256>>>(p_h1, dw_w, dw_b, p_h2);
    mma_gemm<<<dim3(2, ROWS/128), 256, SMEM>>>(p_h2, p_wfc2_h, p_wfc2_l, fc2_b, out,
                                               out, ROWS, CDIM, HID, HID, CDIM, 0, 0);
}

// round 17
// speedup vs baseline: 1.4313x; 1.1790x over previous
#include <cuda_runtime.h>
#include <cuda_bf16.h>
#include <math.h>

// ---------------- problem constants ----------------
#define BATCH 4
#define HW    112
#define NTOK  12544
#define CDIM  256
#define GH    4
#define HD    32
#define GD    128
#define LD    128
#define HID   1024
#define WSZ   7
#define MPOOL 256
#define ROWS  (BATCH*NTOK)
#define ATT_SCALE 0.17677669529663687f

#define PADK  40
#define TILEB (128*PADK)
#define STG   (2*TILEB)          // stage stride: A, B

// ---------------- scratch (device globals; no allocation) ----------------
__device__ __align__(256) __nv_bfloat16 g_xn  [ROWS*CDIM];
__device__ __align__(256) __nv_bfloat16 g_xrn [ROWS*CDIM];
__device__ __align__(256) __nv_bfloat16 g_pool[BATCH*MPOOL*CDIM];
__device__ __align__(256) __nv_bfloat16 g_qq [ROWS*256];          // [Gq | Lq]
__device__ __align__(256) __nv_bfloat16 g_kv [BATCH*MPOOL*2*GD];
__device__ __align__(256) __nv_bfloat16 g_kvl[ROWS*2*LD];
__device__ __align__(256) __nv_bfloat16 g_att[ROWS*256];          // [gattn | lattn]
__device__ __align__(256) float g_cat[ROWS*CDIM];
__device__ __align__(256) __nv_bfloat16 g_ln2[ROWS*CDIM];
__device__ __align__(256) __nv_bfloat16 g_h1 [ROWS*HID];
__device__ __align__(256) __nv_bfloat16 g_h2 [ROWS*HID];
// transposed bf16 weights [N][K] + merged bias
__device__ __align__(256) __nv_bfloat16 w_q  [256*CDIM];
__device__ __align__(256) __nv_bfloat16 w_kv [256*CDIM];
__device__ __align__(256) __nv_bfloat16 w_lkv[256*CDIM];
__device__ __align__(256) __nv_bfloat16 w_gp [GD*GD];
__device__ __align__(256) __nv_bfloat16 w_lp [LD*LD];
__device__ __align__(256) __nv_bfloat16 w_fc1[HID*CDIM];
__device__ __align__(256) __nv_bfloat16 w_fc2[CDIM*HID];
__device__ __align__(256) float b_q[256];

// ---------------- helpers ----------------
__device__ __forceinline__ void bf16_store4(__nv_bfloat16* p, float4 v)
{
    __nv_bfloat162 h0 = __nv_bfloat162(__float2bfloat16(v.x), __float2bfloat16(v.y));
    __nv_bfloat162 h1 = __nv_bfloat162(__float2bfloat16(v.z), __float2bfloat16(v.w));
    ((__nv_bfloat162*)p)[0] = h0;
    ((__nv_bfloat162*)p)[1] = h1;
}

__device__ __forceinline__ float4 bf16_load4(const __nv_bfloat16* p)
{
    __nv_bfloat162 a = ((const __nv_bfloat162*)p)[0];
    __nv_bfloat162 b = ((const __nv_bfloat162*)p)[1];
    float2 fa = __bfloat1622float2(a);
    float2 fb = __bfloat1622float2(b);
    return make_float4(fa.x, fa.y, fb.x, fb.y);
}

__device__ __forceinline__ unsigned smem_u32(const void* p)
{
    return (unsigned)__cvta_generic_to_shared(p);
}

__device__ __forceinline__ void ldsm4(unsigned* r, unsigned addr)
{
    asm volatile("ldmatrix.sync.aligned.m8n8.x4.shared.b16 {%0,%1,%2,%3}, [%4];"
        : "=r"(r[0]), "=r"(r[1]), "=r"(r[2]), "=r"(r[3]) : "r"(addr));
}

__device__ __forceinline__ void mma_bf16(float* c, const unsigned* a, const unsigned* b)
{
    asm volatile("mma.sync.aligned.m16n8k16.row.col.f32.bf16.bf16.f32 "
        "{%0,%1,%2,%3},{%4,%5,%6,%7},{%8,%9},{%0,%1,%2,%3};"
        : "+f"(c[0]), "+f"(c[1]), "+f"(c[2]), "+f"(c[3])
        : "r"(a[0]), "r"(a[1]), "r"(a[2]), "r"(a[3]), "r"(b[0]), "r"(b[1]));
}

__device__ __forceinline__ void cpa16(unsigned saddr, const void* g)
{
    asm volatile("cp.async.cg.shared.global [%0], [%1], 16;" :: "r"(saddr), "l"(g) : "memory");
}

// ---- packed f32x2 math ----
__device__ __forceinline__ void fma2(unsigned long long& d, unsigned long long a,
                                     unsigned long long b)
{
    asm("fma.rn.f32x2 %0, %1, %2, %0;" : "+l"(d) : "l"(a), "l"(b));
}

__device__ __forceinline__ void mul2(unsigned long long& d, unsigned long long c)
{
    asm("mul.rn.f32x2 %0, %0, %1;" : "+l"(d) : "l"(c));
}

__device__ __forceinline__ unsigned long long pack2(float x)
{
    unsigned long long r;
    asm("mov.b64 %0, {%1, %1};" : "=l"(r) : "f"(x));
    return r;
}

__device__ __forceinline__ unsigned long long packf2(float2 f)
{
    unsigned long long r;
    asm("mov.b64 %0, {%1, %2};" : "=l"(r) : "f"(f.x), "f"(f.y));
    return r;
}

__device__ __forceinline__ float2 unpack2(unsigned long long v)
{
    float2 f;
    asm("mov.b64 {%0, %1}, %2;" : "=f"(f.x), "=f"(f.y) : "l"(v));
    return f;
}

// stage loader: 256 threads, 2 tiles (A, B) x 512 16B-chunks
__device__ __forceinline__ void gemm_stage(
    __nv_bfloat16* sbase, int tid,
    const __nv_bfloat16* A, const __nv_bfloat16* B,
    int bm, int bn, int K, int lda, int k0)
{
    __nv_bfloat16* sA = sbase;
    __nv_bfloat16* sB = sbase + TILEB;
    #pragma unroll
    for (int j = 0; j < 2; j++) {
        int u = tid + 256*j;
        int row = u >> 2;
        int qq = u & 3;
        int so = row * PADK + qq * 8;
        size_t gA = (size_t)(bm + row) * lda + k0 + qq * 8;
        size_t gB = (size_t)(bn + row) * K + k0 + qq * 8;
        cpa16(smem_u32(sA + so), A + gA);
        cpa16(smem_u32(sB + so), B + gB);
    }
}

// ---------------- single-launch weight transpose (bf16) ----------------
__global__ void wtrans_all(const float* __restrict__ Gq, const float* __restrict__ Gkv,
                           const float* __restrict__ Gp, const float* __restrict__ Lq,
                           const float* __restrict__ Lkv, const float* __restrict__ Lp,
                           const float* __restrict__ fc1, const float* __restrict__ fc2,
                           const float* __restrict__ Gq_b, const float* __restrict__ Lq_b)
{
    int t = blockIdx.x * blockDim.x + threadIdx.x;
    if (t < 65536) {
        int n = t >> 8;
        int k = t & 255;
        float v = (n < 128) ? Gq[(size_t)k*128 + n] : Lq[(size_t)k*128 + (n-128)];
        w_q[t] = __float2bfloat16(v);
    } else if (t < 131072) {
        int u = t - 65536;
        int n = u >> 8;
        int k = u & 255;
        w_kv[u] = __float2bfloat16(Gkv[(size_t)k*256 + n]);
    } else if (t < 196608) {
        int u = t - 131072;
        int n = u >> 8;
        int k = u & 255;
        w_lkv[u] = __float2bfloat16(Lkv[(size_t)k*256 + n]);
    } else if (t < 212992) {
        int u = t - 196608;
        int n = u >> 7;
        int k = u & 127;
        w_gp[u] = __float2bfloat16(Gp[(size_t)k*128 + n]);
    } else if (t < 229376) {
        int u = t - 212992;
        int n = u >> 7;
        int k = u & 127;
        w_lp[u] = __float2bfloat16(Lp[(size_t)k*128 + n]);
    } else if (t < 491520) {
        int u = t - 229376;
        int n = u >> 8;
        int k = u & 255;
        w_fc1[u] = __float2bfloat16(fc1[(size_t)k*1024 + n]);
    } else if (t < 753664) {
        int u = t - 491520;
        int n = u / 1024;
        int k = u - n * 1024;
        w_fc2[u] = __float2bfloat16(fc2[(size_t)k*256 + n]);
    } else if (t < 753920) {
        int u = t - 753664;
        b_q[u] = (u < 128) ? Gq_b[u] : Lq_b[u-128];
    }
}

// ---------------- LayerNorm (ln1, bf16 out) ----------------
__global__ void ln_kernel(const float* __restrict__ x, const float* __restrict__ g,
                          const float* __restrict__ b,
                          __nv_bfloat16* __restrict__ oh, int rows)
{
    int gw   = (blockIdx.x * blockDim.x + threadIdx.x) >> 5;
    int lane = threadIdx.x & 31;
    if (gw >= rows) return;
    const float4* xr = (const float4*)(x + (size_t)gw * CDIM);
    float4 v0 = xr[lane];
    float4 v1 = xr[lane + 32];
    float s  = v0.x+v0.y+v0.z+v0.w + v1.x+v1.y+v1.z+v1.w;
    float ss = v0.x*v0.x+v0.y*v0.y+v0.z*v0.z+v0.w*v0.w
             + v1.x*v1.x+v1.y*v1.y+v1.z*v1.z+v1.w*v1.w;
    #pragma unroll
    for (int o = 16; o; o >>= 1) {
        s  += __shfl_xor_sync(0xffffffffu, s,  o);
        ss += __shfl_xor_sync(0xffffffffu, ss, o);
    }
    float mean = s * (1.0f/CDIM);
    float var  = ss * (1.0f/CDIM) - mean*mean;
    float inv  = rsqrtf(var + 1e-5f);
    const float4* g4 = (const float4*)g;
    const float4* b4 = (const float4*)b;
    float4 G0 = g4[lane];
    float4 B0 = b4[lane];
    float4 G1 = g4[lane+32];
    float4 B1 = b4[lane+32];
    float4 o0, o1;
    o0.x = (v0.x-mean)*inv*G0.x + B0.x;
    o0.y = (v0.y-mean)*inv*G0.y + B0.y;
    o0.z = (v0.z-mean)*inv*G0.z + B0.z;
    o0.w = (v0.w-mean)*inv*G0.w + B0.w;
    o1.x = (v1.x-mean)*inv*G1.x + B1.x;
    o1.y = (v1.y-mean)*inv*G1.y + B1.y;
    o1.z = (v1.z-mean)*inv*G1.z + B1.z;
    o1.w = (v1.w-mean)*inv*G1.w + B1.w;
    size_t base = (size_t)gw * CDIM + lane * 4;
    bf16_store4(oh + base,       o0);
    bf16_store4(oh + base + 128, o1);
}

// ---------------- fused residual add + LayerNorm (ln2, bf16 out) -------------
__global__ void addln_kernel(const float* __restrict__ x, const float* __restrict__ cat,
                             const float* __restrict__ g, const float* __restrict__ b,
                             float* __restrict__ out, __nv_bfloat16* __restrict__ oh)
{
    int gw   = (blockIdx.x * blockDim.x + threadIdx.x) >> 5;
    int lane = threadIdx.x & 31;
    const float4* xr = (const float4*)(x + (size_t)gw * CDIM);
    const float4* cr = (const float4*)(cat + (size_t)gw * CDIM);
    float4 a0 = xr[lane];
    float4 a1 = xr[lane + 32];
    float4 c0 = cr[lane];
    float4 c1 = cr[lane + 32];
    float4 v0 = make_float4(a0.x+c0.x, a0.y+c0.y, a0.z+c0.z, a0.w+c0.w);
    float4 v1 = make_float4(a1.x+c1.x, a1.y+c1.y, a1.z+c1.z, a1.w+c1.w);
    float4* orow = (float4*)(out + (size_t)gw * CDIM);
    orow[lane]      = v0;
    orow[lane + 32] = v1;
    float s  = v0.x+v0.y+v0.z+v0.w + v1.x+v1.y+v1.z+v1.w;
    float ss = v0.x*v0.x+v0.y*v0.y+v0.z*v0.z+v0.w*v0.w
             + v1.x*v1.x+v1.y*v1.y+v1.z*v1.z+v1.w*v1.w;
    #pragma unroll
    for (int o = 16; o; o >>= 1) {
        s  += __shfl_xor_sync(0xffffffffu, s,  o);
        ss += __shfl_xor_sync(0xffffffffu, ss, o);
    }
    float mean = s * (1.0f/CDIM);
    float var  = ss * (1.0f/CDIM) - mean*mean;
    float inv  = rsqrtf(var + 1e-5f);
    const float4* g4 = (const float4*)g;
    const float4* b4 = (const float4*)b;
    float4 G0 = g4[lane];
    float4 B0 = b4[lane];
    float4 G1 = g4[lane+32];
    float4 B1 = b4[lane+32];
    float4 o0, o1;
    o0.x = (v0.x-mean)*inv*G0.x + B0.x;
    o0.y = (v0.y-mean)*inv*G0.y + B0.y;
    o0.z = (v0.z-mean)*inv*G0.z + B0.z;
    o0.w = (v0.w-mean)*inv*G0.w + B0.w;
    o1.x = (v1.x-mean)*inv*G1.x + B1.x;
    o1.y = (v1.y-mean)*inv*G1.y + B1.y;
    o1.z = (v1.z-mean)*inv*G1.z + B1.z;
    o1.w = (v1.w-mean)*inv*G1.w + B1.w;
    size_t base = (size_t)gw * CDIM + lane * 4;
    bf16_store4(oh + base,       o0);
    bf16_store4(oh + base + 128, o1);
}

// ---------------- 7x7 mean pooling (bf16 in/out) ----------------
__global__ void pool_kernel(const __nv_bfloat16* __restrict__ xh,
                            __nv_bfloat16* __restrict__ ph)
{
    int t = blockIdx.x * blockDim.x + threadIdx.x;
    int c = t & 255;
    int g = (t >> 8) & 255;
    int b = t >> 16;
    int gy = g >> 4;
    int gx = g & 15;
    float s = 0.0f;
    #pragma unroll
    for (int py = 0; py < WSZ; py++) {
        int rowbase = (gy*WSZ + py) * HW + gx*WSZ;
        #pragma unroll
        for (int px = 0; px < WSZ; px++) {
            size_t idx = ((size_t)b*NTOK + rowbase + px) * CDIM + c;
            s += __bfloat162float(xh[idx]);
        }
    }
    ph[t] = __float2bfloat16(s * (1.0f/49.0f));
}

// ---------------- tensor-core pure-bf16 GEMM ----------------
// obf=0: C(float*) = (addsrc?) + A@B^T + bias ; obf=1: C(bf16*), no addsrc
__global__ void __launch_bounds__(256, 2) mma_gemm(
    const __nv_bfloat16* __restrict__ A, const __nv_bfloat16* __restrict__ B,
    const float* __restrict__ bias, const float* __restrict__ addsrc,
    void* __restrict__ Cv, int M, int N, int K, int lda, int ldc, int coff, int obf)
{
    extern __shared__ __nv_bfloat16 sh[];
    int tid  = threadIdx.x;
    int lane = tid & 31;
    int warp = tid >> 5;
    int wm = (warp & 3) * 32;
    int wn = (warp >> 2) * 64;
    int bm = blockIdx.y * 128;
    int bn = blockIdx.x * 128;

    float acc[2][8][4];
    #pragma unroll
    for (int i = 0; i < 2; i++) {
        #pragma unroll
        for (int j = 0; j < 8; j++) {
            #pragma unroll
            for (int e = 0; e < 4; e++) {
                acc[i][j][e] = 0.0f;
            }
        }
    }

    int nIter = K >> 5;

    gemm_stage(sh, tid, A, B, bm, bn, K, lda, 0);
    asm volatile("cp.async.commit_group;" ::: "memory");

    for (int it = 0; it < nIter; it++) {
        int st = it & 1;
        if (it + 1 < nIter) {
            gemm_stage(sh + (st^1)*STG, tid, A, B, bm, bn, K, lda, (it+1) << 5);
            asm volatile("cp.async.commit_group;" ::: "memory");
            asm volatile("cp.async.wait_group 1;" ::: "memory");
        } else {
            asm volatile("cp.async.wait_group 0;" ::: "memory");
        }
        __syncthreads();

        const __nv_bfloat16* cA = sh + st*STG;
        const __nv_bfloat16* cB = cA + TILEB;

        #pragma unroll
        for (int kk = 0; kk < 2; kk++) {
            unsigned af[2][4];
            #pragma unroll
            for (int mi = 0; mi < 2; mi++) {
                int row = wm + mi*16 + (lane & 15);
                int col = kk*16 + (lane >> 4) * 8;
                ldsm4(af[mi], smem_u32(cA + row*PADK + col));
            }
            #pragma unroll
            for (int np = 0; np < 4; np++) {
                unsigned bf[4];
                int row = wn + np*16 + (lane >> 4) * 8 + (lane & 7);
                int col = kk*16 + ((lane >> 3) & 1) * 8;
                ldsm4(bf, smem_u32(cB + row*PADK + col));
                #pragma unroll
                for (int mi = 0; mi < 2; mi++) {
                    mma_bf16(acc[mi][2*np],   af[mi], &bf[0]);
                    mma_bf16(acc[mi][2*np+1], af[mi], &bf[2]);
                }
            }
        }
        __syncthreads();
    }

    int gg = lane >> 2;
    int t2 = (lane & 3) * 2;
    #pragma unroll
    for (int mi = 0; mi < 2; mi++) {
        #pragma unroll
        for (int half = 0; half < 2; half++) {
            int row = bm + wm + mi*16 + gg + half*8;
            #pragma unroll
            for (int ni = 0; ni < 8; ni++) {
                int col = bn + wn + ni*8 + t2;
                float2 bv = *(const float2*)&bias[col];
                float v0 = acc[mi][ni][half*2 + 0] + bv.x;
                float v1 = acc[mi][ni][half*2 + 1] + bv.y;
                size_t off = (size_t)row * ldc + coff + col;
                if (obf) {
                    __nv_bfloat16* Cb = (__nv_bfloat16*)Cv;
                    ((__nv_bfloat162*)&Cb[off])[0] =
                        __nv_bfloat162(__float2bfloat16(v0), __float2bfloat16(v1));
                } else {
                    float* C = (float*)Cv;
                    if (addsrc) {
                        float2 sv = *(const float2*)&addsrc[off];
                        v0 += sv.x;
                        v1 += sv.y;
                    }
                    *(float2*)&C[off] = make_float2(v0, v1);
                }
            }
        }
    }
}

// ---------------- global attention (bf16 q/kv in, bf16 out) ----------------
__global__ void __launch_bounds__(128) gattn_kernel(
    const __nv_bfloat16* __restrict__ q, const __nv_bfloat16* __restrict__ kv,
    __nv_bfloat16* __restrict__ oh)
{
    __shared__ float ks[128][HD];
    __shared__ float vs[128][HD];
    int bi = blockIdx.x;
    int qc = bi % (NTOK/128);
    int h  = (bi / (NTOK/128)) & (GH-1);
    int b  = bi / ((NTOK/128) * GH);
    int tid = threadIdx.x;
    int n   = qc*128 + tid;
    size_t qrow = (size_t)(b*NTOK + n) * 256 + h*HD;

    unsigned long long q2[16];
    {
        const __nv_bfloat162* qp = (const __nv_bfloat162*)&q[qrow];
        #pragma unroll
        for (int j = 0; j < 16; j++) {
            q2[j] = packf2(__bfloat1622float2(qp[j]));
        }
    }

    float mx = -INFINITY;
    float l = 0.0f;
    unsigned long long a2[16];
    #pragma unroll
    for (int d = 0; d < 16; d++) {
        a2[d] = 0ULL;
    }

    for (int ch = 0; ch < 2; ch++) {
        #pragma unroll
        for (int j = 0; j < 8; j++) {
            int f4 = tid + 128*j;
            int m  = f4 >> 3;
            int d4 = (f4 & 7) * 4;
            size_t kvrow = (size_t)(b*MPOOL + ch*128 + m) * (2*GD) + h*HD;
            *(float4*)&ks[m][d4] = bf16_load4(&kv[kvrow + d4]);
            *(float4*)&vs[m][d4] = bf16_load4(&kv[kvrow + GD + d4]);
        }
        __syncthreads();
        for (int m = 0; m < 128; m++) {
            const ulonglong2* kp = (const ulonglong2*)ks[m];
            unsigned long long s0 = 0ULL, s1 = 0ULL, s2 = 0ULL, s3 = 0ULL;
            #pragma unroll
            for (int i = 0; i < 4; i++) {
                ulonglong2 ka = kp[2*i];
                ulonglong2 kb = kp[2*i+1];
                fma2(s0, q2[4*i+0], ka.x);
                fma2(s1, q2[4*i+1], ka.y);
                fma2(s2, q2[4*i+2], kb.x);
                fma2(s3, q2[4*i+3], kb.y);
            }
            float2 f0 = unpack2(s0);
            float2 f1 = unpack2(s1);
            float2 f2 = unpack2(s2);
            float2 f3 = unpack2(s3);
            float sdot = (f0.x + f0.y) + (f1.x + f1.y) + (f2.x + f2.y) + (f3.x + f3.y);
            float sc = sdot * ATT_SCALE;
            if (sc > mx) {
                float corr = __expf(mx - sc);
                l *= corr;
                unsigned long long c2 = pack2(corr);
                #pragma unroll
                for (int d = 0; d < 16; d++) {
                    mul2(a2[d], c2);
                }
                mx = sc;
            }
            float p = __expf(sc - mx);
            l += p;
            unsigned long long p2 = pack2(p);
            const ulonglong2* vp = (const ulonglong2*)vs[m];
            #pragma unroll
            for (int i = 0; i < 8; i++) {
                ulonglong2 va = vp[i];
                fma2(a2[2*i],   p2, va.x);
                fma2(a2[2*i+1], p2, va.y);
            }
        }
        __syncthreads();
    }

    float inv = 1.0f / l;
    #pragma unroll
    for (int j = 0; j < 8; j++) {
        float2 u0 = unpack2(a2[2*j]);
        float2 u1 = unpack2(a2[2*j+1]);
        bf16_store4(oh + qrow + 4*j, make_float4(u0.x*inv, u0.y*inv, u1.x*inv, u1.y*inv));
    }
}

// ---------------- local window attention (bf16 q/kv in, bf16 out) ------------
__global__ void __launch_bounds__(128) lattn_kernel(
    const __nv_bfloat16* __restrict__ ql, const __nv_bfloat16* __restrict__ kvl,
    __nv_bfloat16* __restrict__ oh)
{
    __shared__ float ks[2][49][HD];
    __shared__ float vs[2][49][HD];
    int bi = blockIdx.x;
    int hp = bi & 1;
    int wi = (bi >> 1) & 255;
    int b  = bi >> 9;
    int wy = wi >> 4;
    int wx = wi & 15;
    int tid = threadIdx.x;

    for (int i = tid; i < 2*49*8; i += 128) {
        int d4 = (i & 7) * 4;
        int t  = (i >> 3) % 49;
        int hh = i / (49*8);
        int py = t / WSZ;
        int px = t % WSZ;
        int n  = (wy*WSZ + py)*HW + wx*WSZ + px;
        size_t rowb = (size_t)(b*NTOK + n) * (2*LD) + (hp*2 + hh)*HD;
        *(float4*)&ks[hh][t][d4] = bf16_load4(&kvl[rowb + d4]);
        *(float4*)&vs[hh][t][d4] = bf16_load4(&kvl[rowb + LD + d4]);
    }
    __syncthreads();

    if (tid < 98) {
        int hh = tid / 49;
        int qi = tid % 49;
        int h  = hp*2 + hh;
        int py = qi / WSZ;
        int px = qi % WSZ;
        int n  = (wy*WSZ + py)*HW + wx*WSZ + px;
        size_t qrow = (size_t)(b*NTOK + n) * 256 + 128 + h*HD;

        unsigned long long q2[16];
        {
            const __nv_bfloat162* qp = (const __nv_bfloat162*)&ql[qrow];
            #pragma unroll
            for (int j = 0; j < 16; j++) {
                q2[j] = packf2(__bfloat1622float2(qp[j]));
            }
        }

        float sc[49];
        float mx = -INFINITY;
        #pragma unroll
        for (int t = 0; t < 49; t++) {
            const ulonglong2* kp = (const ulonglong2*)ks[hh][t];
            unsigned long long s0 = 0ULL, s1 = 0ULL, s2 = 0ULL, s3 = 0ULL;
            #pragma unroll
            for (int i = 0; i < 4; i++) {
                ulonglong2 ka = kp[2*i];
                ulonglong2 kb = kp[2*i+1];
                fma2(s0, q2[4*i+0], ka.x);
                fma2(s1, q2[4*i+1], ka.y);
                fma2(s2, q2[4*i+2], kb.x);
                fma2(s3, q2[4*i+3], kb.y);
            }
            float2 f0 = unpack2(s0);
            float2 f1 = unpack2(s1);
            float2 f2 = unpack2(s2);
            float2 f3 = unpack2(s3);
            float s = ((f0.x + f0.y) + (f1.x + f1.y) + (f2.x + f2.y) + (f3.x + f3.y)) * ATT_SCALE;
            sc[t] = s;
            mx = fmaxf(mx, s);
        }
        float l = 0.0f;
        #pragma unroll
        for (int t = 0; t < 49; t++) {
            sc[t] = __expf(sc[t] - mx);
            l += sc[t];
        }
        float inv = 1.0f / l;

        unsigned long long a2[16];
        #pragma unroll
        for (int d = 0; d < 16; d++) {
            a2[d] = 0ULL;
        }
        #pragma unroll
        for (int t = 0; t < 49; t++) {
            unsigned long long p2 = pack2(sc[t] * inv);
            const ulonglong2* vp = (const ulonglong2*)vs[hh][t];
            #pragma unroll
            for (int i = 0; i < 8; i++) {
                ulonglong2 va = vp[i];
                fma2(a2[2*i],   p2, va.x);
                fma2(a2[2*i+1], p2, va.y);
            }
        }
        #pragma unroll
        for (int j = 0; j < 8; j++) {
            float2 u0 = unpack2(a2[2*j]);
            float2 u1 = unpack2(a2[2*j+1]);
            bf16_store4(oh + qrow + 4*j, make_float4(u0.x, u0.y, u1.x, u1.y));
        }
    }
}

// ---------------- depthwise 3x3 conv + exact GELU, 4-row blocked -------------
__device__ __forceinline__ float gelu_exact(float v)
{
    return 0.5f * v * (1.0f + erff(v * 0.70710678118654752f));
}

__global__ void dwconv_gelu_kernel(const __nv_bfloat16* __restrict__ h,
                                   const float* __restrict__ w,
                                   const float* __restrict__ bias,
                                   __nv_bfloat16* __restrict__ oh)
{
    int t = blockIdx.x * blockDim.x + threadIdx.x;
    int c4 = t & 255;
    int rest = t >> 8;
    int xx = rest % HW;
    int tmp = rest / HW;
    int y4 = tmp % (HW/4);
    int bb = tmp / (HW/4);
    int yy0 = y4 * 4;
    int c  = c4 * 4;

    float wv[4][9];
    #pragma unroll
    for (int e = 0; e < 4; e++) {
        #pragma unroll
        for (int k = 0; k < 9; k++) {
            wv[e][k] = w[(c+e)*9 + k];
        }
    }

    float4 bz = *(const float4*)&bias[c];
    float4 acc[4];
    #pragma unroll
    for (int oy = 0; oy < 4; oy++) {
        acc[oy] = bz;
    }

    #pragma unroll
    for (int ry = 0; ry < 6; ry++) {
        int y2 = yy0 - 1 + ry;
        if ((unsigned)y2 >= HW) continue;
        #pragma unroll
        for (int dx = 0; dx < 3; dx++) {
            int x2 = xx + dx - 1;
            if ((unsigned)x2 >= HW) continue;
            float4 v = bf16_load4(&h[((size_t)bb*NTOK + y2*HW + x2) * HID + c]);
            #pragma unroll
            for (int oy = 0; oy < 4; oy++) {
                int dy = ry - oy;
                if (dy < 0 || dy > 2) continue;
                int k = dy*3 + dx;
                acc[oy].x = fmaf(v.x, wv[0][k], acc[oy].x);
                acc[oy].y = fmaf(v.y, wv[1][k], acc[oy].y);
                acc[oy].z = fmaf(v.z, wv[2][k], acc[oy].z);
                acc[oy].w = fmaf(v.w, wv[3][k], acc[oy].w);
            }
        }
    }

    #pragma unroll
    for (int oy = 0; oy < 4; oy++) {
        float4 a = acc[oy];
        a.x = gelu_exact(a.x);
        a.y = gelu_exact(a.y);
        a.z = gelu_exact(a.z);
        a.w = gelu_exact(a.w);
        size_t off = ((size_t)bb*NTOK + (yy0+oy)*HW + xx) * HID + c;
        bf16_store4(oh + off, a);
    }
}

// ---------------- persistent host objects (created once, reused) -------------
static cudaStream_t h_s1 = 0;
static cudaStream_t h_s2 = 0;
static cudaEvent_t  h_e_wt = 0, h_e_ln = 0, h_e_q = 0, h_e_gkv = 0, h_e_lp = 0, h_e_fork = 0;
static int h_objs_ready = 0;

// ---------------- launch (stream-parallel DAG inside graph capture) ----------
extern "C" void kernel_launch(void* const* d_in, const int* in_sizes, int n_in,
                              void* d_out, int out_size)
{
    const float* x     = (const float*)d_in[0];
    const float* xr    = (const float*)d_in[1];
    const float* g1    = (const float*)d_in[2];
    const float* b1    = (const float*)d_in[3];
    const float* g2    = (const float*)d_in[4];
    const float* b2    = (const float*)d_in[5];
    const float* Gq_w  = (const float*)d_in[6];
    const float* Gq_b  = (const float*)d_in[7];
    const float* Gkv_w = (const float*)d_in[8];
    const float* Gkv_b = (const float*)d_in[9];
    const float* Gp_w  = (const float*)d_in[10];
    const float* Gp_b  = (const float*)d_in[11];
    const float* Lq_w  = (const float*)d_in[12];
    const float* Lq_b  = (const float*)d_in[13];
    const float* Lkv_w = (const float*)d_in[14];
    const float* Lkv_b = (const float*)d_in[15];
    const float* Lp_w  = (const float*)d_in[16];
    const float* Lp_b  = (const float*)d_in[17];
    const float* fc1_w = (const float*)d_in[18];
    const float* fc1_b = (const float*)d_in[19];
    const float* dw_w  = (const float*)d_in[20];
    const float* dw_b  = (const float*)d_in[21];
    const float* fc2_w = (const float*)d_in[22];
    const float* fc2_b = (const float*)d_in[23];
    float* out = (float*)d_out;

    __nv_bfloat16 *p_xn;
    __nv_bfloat16 *p_xrn;
    __nv_bfloat16 *p_pool;
    __nv_bfloat16 *p_att;
    __nv_bfloat16 *p_ln2;
    __nv_bfloat16 *p_h1;
    __nv_bfloat16 *p_h2;
    __nv_bfloat16 *p_qq;
    __nv_bfloat16 *p_kv;
    __nv_bfloat16 *p_kvl;
    float *p_cat;
    float *p_bq;
    __nv_bfloat16 *p_wq;
    __nv_bfloat16 *p_wkv;
    __nv_bfloat16 *p_wlkv;
    __nv_bfloat16 *p_wgp;
    __nv_bfloat16 *p_wlp;
    __nv_bfloat16 *p_wfc1;
    __nv_bfloat16 *p_wfc2;

    cudaGetSymbolAddress((void**)&p_xn, g_xn);
    cudaGetSymbolAddress((void**)&p_xrn, g_xrn);
    cudaGetSymbolAddress((void**)&p_pool, g_pool);
    cudaGetSymbolAddress((void**)&p_att, g_att);
    cudaGetSymbolAddress((void**)&p_ln2, g_ln2);
    cudaGetSymbolAddress((void**)&p_h1, g_h1);
    cudaGetSymbolAddress((void**)&p_h2, g_h2);
    cudaGetSymbolAddress((void**)&p_qq, g_qq);
    cudaGetSymbolAddress((void**)&p_kv, g_kv);
    cudaGetSymbolAddress((void**)&p_kvl, g_kvl);
    cudaGetSymbolAddress((void**)&p_cat, g_cat);
    cudaGetSymbolAddress((void**)&p_bq, b_q);
    cudaGetSymbolAddress((void**)&p_wq, w_q);
    cudaGetSymbolAddress((void**)&p_wkv, w_kv);
    cudaGetSymbolAddress((void**)&p_wlkv, w_lkv);
    cudaGetSymbolAddress((void**)&p_wgp, w_gp);
    cudaGetSymbolAddress((void**)&p_wlp, w_lp);
    cudaGetSymbolAddress((void**)&p_wfc1, w_fc1);
    cudaGetSymbolAddress((void**)&p_wfc2, w_fc2);

    const int SMEM = 2 * STG * (int)sizeof(__nv_bfloat16);   // 40960
    cudaFuncSetAttribute(mma_gemm, cudaFuncAttributeMaxDynamicSharedMemorySize, SMEM);

    if (!h_objs_ready) {
        cudaStreamCreateWithFlags(&h_s1, cudaStreamNonBlocking);
        cudaStreamCreateWithFlags(&h_s2, cudaStreamNonBlocking);
        cudaEventCreateWithFlags(&h_e_wt,   cudaEventDisableTiming);
        cudaEventCreateWithFlags(&h_e_ln,   cudaEventDisableTiming);
        cudaEventCreateWithFlags(&h_e_q,    cudaEventDisableTiming);
        cudaEventCreateWithFlags(&h_e_gkv,  cudaEventDisableTiming);
        cudaEventCreateWithFlags(&h_e_lp,   cudaEventDisableTiming);
        cudaEventCreateWithFlags(&h_e_fork, cudaEventDisableTiming);
        h_objs_ready = 1;
    }
    cudaStream_t s1 = h_s1;
    cudaStream_t s2 = h_s2;

    // fork s1/s2 off the capture stream so they join the capture
    cudaEventRecord(h_e_fork, 0);
    cudaStreamWaitEvent(s1, h_e_fork, 0);
    cudaStreamWaitEvent(s2, h_e_fork, 0);

    // s1: weight transpose (independent of LN)
    wtrans_all<<<2945, 256, 0, s1>>>(Gq_w, Gkv_w, Gp_w, Lq_w, Lkv_w, Lp_w,
                                     fc1_w, fc2_w, Gq_b, Lq_b);
    cudaEventRecord(h_e_wt, s1);

    // s0: both LayerNorms
    ln_kernel<<<ROWS/8, 256>>>(x,  g1, b1, p_xn,  ROWS);
    ln_kernel<<<ROWS/8, 256>>>(xr, g1, b1, p_xrn, ROWS);
    cudaEventRecord(h_e_ln, 0);

    // s0: Q projection (bf16 out)
    cudaStreamWaitEvent(0, h_e_wt, 0);
    mma_gemm<<<dim3(2, ROWS/128), 256, SMEM>>>(p_xn, p_wq, p_bq, 0,
                                               p_qq, ROWS, 256, CDIM, CDIM, 256, 0, 1);
    cudaEventRecord(h_e_q, 0);

    // s2: pool -> Gkv (bf16 out)
    cudaStreamWaitEvent(s2, h_e_ln, 0);
    cudaStreamWaitEvent(s2, h_e_wt, 0);
    pool_kernel<<<(BATCH*MPOOL*CDIM)/256, 256, 0, s2>>>(p_xrn, p_pool);
    mma_gemm<<<dim3(2, (BATCH*MPOOL)/128), 256, SMEM, s2>>>(p_pool, p_wkv, Gkv_b, 0,
                                               p_kv, BATCH*MPOOL, 2*GD, CDIM, CDIM, 2*GD, 0, 1);
    cudaEventRecord(h_e_gkv, s2);

    // s1: Lkv projection (bf16 out)
    cudaStreamWaitEvent(s1, h_e_ln, 0);
    mma_gemm<<<dim3(2, ROWS/128), 256, SMEM, s1>>>(p_xrn, p_wlkv, Lkv_b, 0,
                                               p_kvl, ROWS, 2*LD, CDIM, CDIM, 2*LD, 0, 1);

    // s0: global attention (needs Q on s0, Gkv on s2)
    cudaStreamWaitEvent(0, h_e_gkv, 0);
    gattn_kernel<<<BATCH*GH*(NTOK/128), 128>>>(p_qq, p_kv, p_att);
    // s0: Gp projection (fp32 out into cat)
    mma_gemm<<<dim3(1, ROWS/128), 256, SMEM>>>(p_att, p_wgp, Gp_b, 0,
                                               p_cat, ROWS, GD, GD, 256, CDIM, 0, 0);

    // s1: local attention (needs Q via e_q; Lkv on s1) then Lp
    cudaStreamWaitEvent(s1, h_e_q, 0);
    lattn_kernel<<<BATCH*256*2, 128, 0, s1>>>(p_qq, p_kvl, p_att);
    mma_gemm<<<dim3(1, ROWS/128), 256, SMEM, s1>>>(p_att + 128, p_wlp, Lp_b, 0,
                                               p_cat, ROWS, LD, LD, 256, CDIM, GD, 0);
    cudaEventRecord(h_e_lp, s1);

    // s0: join Lp, then fused residual add + ln2, FC1 (bf16 out), dwconv, FC2
    cudaStreamWaitEvent(0, h_e_lp, 0);
    addln_kernel<<<ROWS/8, 256>>>(x, p_cat, g2, b2, out, p_ln2);
    mma_gemm<<<dim3(8, ROWS/128), 256, SMEM>>>(p_ln2, p_wfc1, fc1_b, 0,
                                               p_h1, ROWS, HID, CDIM, CDIM, HID, 0, 1);
    dwconv_gelu_kernel<<<(BATCH*(HW/4)*HW*256)/256, 256>>>(p_h1, dw_w, dw_b, p_h2);
    mma_gemm<<<dim3(2, ROWS/128), 256, SMEM>>>(p_h2, p_wfc2, fc2_b, out,
                                               out, ROWS, CDIM, HID, HID, CDIM, 0, 0);
}